// round 6
// baseline (speedup 1.0000x reference)
#include <cuda_runtime.h>
#include <cuda_fp16.h>
#include <cstdint>
#include <math.h>

#define B_  128
#define T_  480
#define C1  64
#define C2  128
#define C3  128

#define S1_ (B_*T_*C1)
#define S2_ (B_*T_*C2)
#define S3_ (B_*T_*C3)

// Padded fp16 spike buffers (rows padded for dilated taps).
#define P1F 64
#define R1_ (P1F + T_ + 160)      // 704 rows  (conv2 max row 637)
#define P2F 192
#define R2_ (P2F + T_ + 608)      // 1280 rows (conv3 max row 889)

#define LO_SCALE 2048.0f
#define LO_INV   (1.0f/2048.0f)

// ---------------- device scratch (allocation-free) ----------------
__device__ float g_x1[S1_];
__device__ float g_x2[S2_];
__device__ float g_x3[S3_];
__device__ __align__(256) __half g_s1h[B_*R1_*C1];
__device__ __align__(256) __half g_s2h[B_*R2_*C2];
__device__ __align__(256) __half g_wt2[2*128*2048];   // [limb][o][kk]
__device__ __align__(256) __half g_wt3[2*128*4096];

// ---------------- PTX helpers (sm_80-era features only) ----------------
__device__ __forceinline__ uint32_t smem_to_u32(const void* p) {
    uint32_t a;
    asm("{ .reg .u64 t; cvta.to.shared.u64 t, %1; cvt.u32.u64 %0, t; }" : "=r"(a) : "l"(p));
    return a;
}
#define SWZ(x) ((x) ^ (((x) >> 3) & 0x70))

#define CP_ASYNC16(sa, gp) \
    asm volatile("cp.async.cg.shared.global [%0], [%1], 16;" \
        :: "r"(sa), "l"(__cvta_generic_to_global(gp)) : "memory")
#define CP_COMMIT() asm volatile("cp.async.commit_group;" ::: "memory")
#define CP_WAIT2()  asm volatile("cp.async.wait_group 2;" ::: "memory")
#define CP_WAIT1()  asm volatile("cp.async.wait_group 1;" ::: "memory")
#define CP_WAIT0()  asm volatile("cp.async.wait_group 0;" ::: "memory")

#define LDSM_X4(r, addr) \
    asm volatile("ldmatrix.sync.aligned.m8n8.x4.shared.b16 {%0,%1,%2,%3}, [%4];" \
        : "=r"((r)[0]), "=r"((r)[1]), "=r"((r)[2]), "=r"((r)[3]) : "r"(addr))

#define MMA16816(c, a, b0, b1) \
    asm volatile("mma.sync.aligned.m16n8k16.row.col.f32.f16.f16.f32 " \
        "{%0,%1,%2,%3}, {%4,%5,%6,%7}, {%8,%9}, {%0,%1,%2,%3};" \
        : "+f"((c)[0]), "+f"((c)[1]), "+f"((c)[2]), "+f"((c)[3]) \
        : "r"((a)[0]), "r"((a)[1]), "r"((a)[2]), "r"((a)[3]), "r"(b0), "r"(b1))

// ---------------------------------------------------------------------------
// conv1 + BN1 (tiny, fp32 CUDA cores)
// ---------------------------------------------------------------------------
__global__ __launch_bounds__(256)
void conv1_bn_kernel(const float* __restrict__ x, const float* __restrict__ w1,
                     const float* __restrict__ sc, const float* __restrict__ bi,
                     const float* __restrict__ mn, const float* __restrict__ vr,
                     float* __restrict__ out) {
    __shared__ float ws[64*64];
    __shared__ float xs[4][64];
    int tid = threadIdx.y*64 + threadIdx.x;
    for (int e = tid; e < 4096; e += 256) ws[e] = w1[e];
    int row = blockIdx.x*4 + threadIdx.y;
    xs[threadIdx.y][threadIdx.x] = x[row*64 + threadIdx.x];
    __syncthreads();
    int o = threadIdx.x;
    float acc = 0.f;
    #pragma unroll 16
    for (int w = 0; w < 64; w++) acc = fmaf(xs[threadIdx.y][w], ws[w*64 + o], acc);
    float inv = rsqrtf(vr[o] + 1e-5f);
    float g = sc[o]*inv;
    out[row*64 + o] = (acc - mn[o])*g + bi[o];
}

// ---------------------------------------------------------------------------
// Weight prep: transpose + 2-limb fp16 split (lo limb scaled by 2048).
// ---------------------------------------------------------------------------
__global__ void wprep_kernel(const float* __restrict__ w, __half* __restrict__ wt,
                             int KTOT) {
    int idx = blockIdx.x*256 + threadIdx.x;
    if (idx >= 128*KTOT) return;
    int o = idx / KTOT, kk = idx % KTOT;
    float v = w[(long)kk*128 + o];
    __half hi = __float2half(v);
    __half lo = __float2half((v - __half2float(hi)) * LO_SCALE);
    wt[idx] = hi;
    wt[(long)128*KTOT + idx] = lo;
}

// ---------------------------------------------------------------------------
// HLIF scan, float4 (4 channels/thread), 32-thread blocks, prefetch 8 steps.
// ---------------------------------------------------------------------------
template<int C, int Rp, int PFp>
__global__ __launch_bounds__(32)
void hlif4_kernel(const float* __restrict__ xin, float* __restrict__ spk,
                  __half* __restrict__ spkh,
                  const float* __restrict__ vth_raw,
                  const float* __restrict__ decay_raw,
                  float v_m, float v_s, float d_m, float d_s) {
    constexpr int NC4 = C/4;
    int idx = blockIdx.x*32 + threadIdx.x;
    int b = idx / NC4, c = (idx % NC4)*4;
    float vth[4], dec[4];
    #pragma unroll
    for (int j = 0; j < 4; j++) {
        vth[j] = log1pf(expf(vth_raw[c+j]*v_s + v_m)) + 0.5f;
        dec[j] = fminf(1.f/(1.f + expf(-(decay_raw[c+j]*d_s + d_m))), 0.99f);
    }
    const float* xp = xin + (long)b*T_*C + c;
    float* sp = spk + (long)b*T_*C + c;
    __half* hp = spkh + ((long)b*Rp + PFp)*C + c;
    float v[4] = {0.f, 0.f, 0.f, 0.f};
    float4 cur[8], nxt[8];
    #pragma unroll
    for (int j = 0; j < 8; j++) cur[j] = *(const float4*)(xp + (long)j*C);
    for (int t = 0; t < T_; t += 8) {
        if (t + 8 < T_) {
            #pragma unroll
            for (int j = 0; j < 8; j++) nxt[j] = *(const float4*)(xp + (long)(t+8+j)*C);
        }
        #pragma unroll
        for (int j = 0; j < 8; j++) {
            float xx[4] = {cur[j].x, cur[j].y, cur[j].z, cur[j].w};
            float s[4];
            #pragma unroll
            for (int k = 0; k < 4; k++) {
                v[k] = v[k]*dec[k] + xx[k];
                s[k] = (v[k] - vth[k]) > 0.f ? 1.f : 0.f;
                v[k] -= s[k]*vth[k];
            }
            *(float4*)(sp + (long)(t+j)*C) = make_float4(s[0], s[1], s[2], s[3]);
            union { __half2 h2[2]; uint2 u; } pk;
            pk.h2[0] = __floats2half2_rn(s[0], s[1]);
            pk.h2[1] = __floats2half2_rn(s[2], s[3]);
            *(uint2*)(hp + (long)(t+j)*C) = pk.u;
        }
        #pragma unroll
        for (int j = 0; j < 8; j++) cur[j] = nxt[j];
    }
}

// ---------------------------------------------------------------------------
// ALIF scan, float4, 32-thread blocks, prefetch 8 steps.
// ---------------------------------------------------------------------------
__global__ __launch_bounds__(32)
void alif4_kernel(const float* __restrict__ xin, float* __restrict__ spk) {
    const float d = 0.9f, adp = 0.9f, beta = 1.8f;
    int idx = blockIdx.x*32 + threadIdx.x;
    int b = idx / (C3/4), c = (idx % (C3/4))*4;
    const float* xp = xin + (long)b*T_*C3 + c;
    float* sp = spk + (long)b*T_*C3 + c;
    float v[4] = {0.f,0.f,0.f,0.f}, th[4] = {0.f,0.f,0.f,0.f}, ps[4] = {0.f,0.f,0.f,0.f};
    float4 cur[8], nxt[8];
    #pragma unroll
    for (int j = 0; j < 8; j++) cur[j] = *(const float4*)(xp + (long)j*C3);
    for (int t = 0; t < T_; t += 8) {
        if (t + 8 < T_) {
            #pragma unroll
            for (int j = 0; j < 8; j++) nxt[j] = *(const float4*)(xp + (long)(t+8+j)*C3);
        }
        #pragma unroll
        for (int j = 0; j < 8; j++) {
            float xx[4] = {cur[j].x, cur[j].y, cur[j].z, cur[j].w};
            float s[4];
            #pragma unroll
            for (int k = 0; k < 4; k++) {
                th[k] = th[k]*adp + ps[k]*beta;
                v[k]  = v[k]*d + xx[k];
                float vt = 0.5f + th[k];
                s[k] = (v[k] - vt) > 0.f ? 1.f : 0.f;
                v[k] -= s[k]*vt;
                ps[k] = s[k];
            }
            *(float4*)(sp + (long)(t+j)*C3) = make_float4(s[0], s[1], s[2], s[3]);
        }
        #pragma unroll
        for (int j = 0; j < 8; j++) cur[j] = nxt[j];
    }
}

// ---------------------------------------------------------------------------
// HMMA dilated conv + BN. 4-stage cp.async pipeline, safe issue-after-sync.
// grid (8 m-tiles, 1, B). CTA tile 64(t) x 128(cout). K chunks of 64.
// 8 warps in 2(M) x 4(N); warp tile 32 x 32. Hi/lo fp16 limbs -> separate
// fp32 accumulators; combined in the epilogue.
// Stage = A(8KB) + Bhi(16KB) + Blo(16KB) = 40KB; x4 stages = 160KB dynamic.
// ---------------------------------------------------------------------------
#define STAGE_BYTES 40960
#define CSMEM_BYTES (4*STAGE_BYTES)

template<int CIN, int DIL, int PADL, int PF, int Rp, int NITER>
__global__ __launch_bounds__(256)
void conv_mma_kernel(const __half* __restrict__ src, const __half* __restrict__ wt,
                     const float* __restrict__ sc, const float* __restrict__ bi,
                     const float* __restrict__ mn, const float* __restrict__ vr,
                     float* __restrict__ dst) {
    constexpr int KTOT = NITER*64;
    constexpr int CHUNKS = CIN/64;
    extern __shared__ char smem[];
    __shared__ float gsm[128], hbm[128];
    const int tid = threadIdx.x, lane = tid & 31, wid = tid >> 5;
    const int warpM = wid >> 2, warpN = wid & 3;
    const int mtile = blockIdx.x, b = blockIdx.z;

    if (tid < 128) {
        float inv = rsqrtf(vr[tid] + 1e-5f);
        float g = sc[tid]*inv;
        gsm[tid] = g;
        hbm[tid] = bi[tid] - mn[tid]*g;
    }

    const uint32_t sbase = smem_to_u32(smem);
    const __half* sb = src + (long)b*Rp*CIN;

    float accH[2][4][4] = {};
    float accL[2][4][4] = {};

    auto issue = [&](int it) {
        const uint32_t stage = sbase + (uint32_t)(it & 3)*(uint32_t)STAGE_BYTES;
        const int k  = it / CHUNKS;
        const int c0 = (it % CHUNKS)*64;
        const long arow0 = (long)(PF + mtile*64 + k*DIL - PADL);
        #pragma unroll
        for (int rep = 0; rep < 2; rep++) {
            int idx = rep*256 + tid;
            int row = idx >> 3, seg = idx & 7;
            const __half* gp = sb + (arow0 + row)*CIN + c0 + seg*8;
            CP_ASYNC16(stage + SWZ(row*128 + seg*16), gp);
        }
        #pragma unroll
        for (int rep = 0; rep < 8; rep++) {
            int idx = rep*256 + tid;                 // 0..2047
            int limb = idx >> 10, rem = idx & 1023;
            int row = rem >> 3, seg = rem & 7;
            const __half* gp = wt + (long)limb*128*KTOT + (long)row*KTOT + it*64 + seg*8;
            CP_ASYNC16(stage + 8192u + (uint32_t)limb*16384u + SWZ(row*128 + seg*16), gp);
        }
        CP_COMMIT();
    };

    issue(0);
    issue(1);
    issue(2);
    __syncthreads();  // covers gsm/hbm writes too

    for (int it = 0; it < NITER; it++) {
        if (it < NITER - 2)       CP_WAIT2();
        else if (it == NITER - 2) CP_WAIT1();
        else                      CP_WAIT0();
        __syncthreads();
        if (it + 3 < NITER) issue(it + 3);   // slot (it+3)&3 computed at it-1: safe

        const uint32_t stage = sbase + (uint32_t)(it & 3)*(uint32_t)STAGE_BYTES;

        #pragma unroll
        for (int ks = 0; ks < 4; ks++) {
            uint32_t a[2][4];
            #pragma unroll
            for (int mf = 0; mf < 2; mf++) {
                int row = warpM*32 + mf*16 + (lane & 15);
                LDSM_X4(a[mf], stage + SWZ(row*128 + ks*32 + (lane >> 4)*16));
            }
            #pragma unroll
            for (int limb = 0; limb < 2; limb++) {
                const uint32_t bbp = stage + 8192u + (uint32_t)limb*16384u;
                #pragma unroll
                for (int np = 0; np < 2; np++) {
                    int row = warpN*32 + np*16 + ((lane >> 4) << 3) + (lane & 7);
                    uint32_t q[4];
                    LDSM_X4(q, bbp + SWZ(row*128 + ks*32 + ((lane >> 3) & 1)*16));
                    if (limb == 0) {
                        #pragma unroll
                        for (int mf = 0; mf < 2; mf++) {
                            MMA16816(accH[mf][np*2],     a[mf], q[0], q[1]);
                            MMA16816(accH[mf][np*2 + 1], a[mf], q[2], q[3]);
                        }
                    } else {
                        #pragma unroll
                        for (int mf = 0; mf < 2; mf++) {
                            MMA16816(accL[mf][np*2],     a[mf], q[0], q[1]);
                            MMA16816(accL[mf][np*2 + 1], a[mf], q[2], q[3]);
                        }
                    }
                }
            }
        }
    }

    // Epilogue: combine limbs, BN, write fp32 pre-activations
    #pragma unroll
    for (int mf = 0; mf < 2; mf++) {
        #pragma unroll
        for (int h = 0; h < 2; h++) {
            int t = mtile*64 + warpM*32 + mf*16 + (lane >> 2) + h*8;
            if (t < T_) {
                long dr = ((long)b*T_ + t)*128;
                #pragma unroll
                for (int ng = 0; ng < 4; ng++) {
                    int col = warpN*32 + ng*8 + (lane & 3)*2;
                    float v0 = fmaf(accL[mf][ng][h*2],     LO_INV, accH[mf][ng][h*2]);
                    float v1 = fmaf(accL[mf][ng][h*2 + 1], LO_INV, accH[mf][ng][h*2 + 1]);
                    float2 o;
                    o.x = fmaf(v0, gsm[col],   hbm[col]);
                    o.y = fmaf(v1, gsm[col+1], hbm[col+1]);
                    *(float2*)&dst[dr + col] = o;
                }
            }
        }
    }
}

// ---------------------------------------------------------------------------
// Readout: dense -> LI scan -> window diff -> attention -> logits
// ---------------------------------------------------------------------------
__global__ __launch_bounds__(256)
void readout_kernel(const float* __restrict__ spk3,
                    const float* __restrict__ dw, const float* __restrict__ db,
                    const float* __restrict__ a1w, const float* __restrict__ a1b,
                    const float* __restrict__ a2w, const float* __restrict__ a2b,
                    float* __restrict__ logits) {
    __shared__ float vseq[T_*4];
    __shared__ float dp[20*4];
    __shared__ float hsm[20*8];
    __shared__ float score[20];
    __shared__ float wsm[128*4];
    int b = blockIdx.x, tid = threadIdx.x;
    for (int e = tid; e < 512; e += 256) wsm[e] = dw[e];
    __syncthreads();
    const float* sp = spk3 + (long)b*T_*C3;
    for (int e = tid; e < T_*4; e += 256) {
        int t = e >> 2, j = e & 3;
        float accv = db[j];
        const float* row = sp + (long)t*C3;
        #pragma unroll 8
        for (int c = 0; c < 128; c++) accv = fmaf(row[c], wsm[c*4 + j], accv);
        vseq[e] = accv;
    }
    __syncthreads();
    if (tid < 4) {
        float v = 0.f;
        const float dec = 0.9f, odec = 0.1f;
        for (int t = 0; t < T_; t++) {
            v = fmaf(v, dec, vseq[t*4 + tid]*odec);
            vseq[t*4 + tid] = v;
        }
    }
    __syncthreads();
    if (tid < 80) {
        int g = tid >> 2, j = tid & 3;
        float s1 = 0.f, s2 = 0.f;
        #pragma unroll
        for (int u = 0; u < 12; u++) {
            s1 += vseq[(g*24 + u)*4 + j];
            s2 += vseq[(g*24 + 12 + u)*4 + j];
        }
        dp[g*4 + j] = (s2 - s1)*(1.f/12.f);
    }
    __syncthreads();
    if (tid < 160) {
        int g = tid >> 3, u = tid & 7;
        float a = a1b[u];
        #pragma unroll
        for (int j = 0; j < 4; j++) a = fmaf(dp[g*4 + j], a1w[j*8 + u], a);
        hsm[g*8 + u] = fmaxf(a, 0.f);
    }
    __syncthreads();
    if (tid < 20) {
        float a = a2b[0];
        #pragma unroll
        for (int u = 0; u < 8; u++) a = fmaf(hsm[tid*8 + u], a2w[u], a);
        score[tid] = a;
    }
    __syncthreads();
    if (tid < 4) {
        float m = -1e30f;
        #pragma unroll
        for (int g = 0; g < 20; g++) m = fmaxf(m, score[g]);
        float den = 0.f, accv = 0.f;
        #pragma unroll
        for (int g = 0; g < 20; g++) {
            float e = expf(score[g] - m);
            den += e;
            accv = fmaf(dp[g*4 + tid], e, accv);
        }
        logits[b*4 + tid] = accv/den;
    }
}

// ---------------------------------------------------------------------------
extern "C" void kernel_launch(void* const* d_in, const int* in_sizes, int n_in,
                              void* d_out, int out_size) {
    const float* x    = (const float*)d_in[0];
    const float* w1   = (const float*)d_in[1];
    const float* bn1s = (const float*)d_in[2];
    const float* bn1b = (const float*)d_in[3];
    const float* bn1m = (const float*)d_in[4];
    const float* bn1v = (const float*)d_in[5];
    const float* vth1 = (const float*)d_in[6];
    const float* dec1 = (const float*)d_in[7];
    const float* w2   = (const float*)d_in[8];
    const float* bn2s = (const float*)d_in[9];
    const float* bn2b = (const float*)d_in[10];
    const float* bn2m = (const float*)d_in[11];
    const float* bn2v = (const float*)d_in[12];
    const float* vth2 = (const float*)d_in[13];
    const float* dec2 = (const float*)d_in[14];
    const float* w3   = (const float*)d_in[15];
    const float* bn3s = (const float*)d_in[16];
    const float* bn3b = (const float*)d_in[17];
    const float* bn3m = (const float*)d_in[18];
    const float* bn3v = (const float*)d_in[19];
    const float* dw   = (const float*)d_in[20];
    const float* db   = (const float*)d_in[21];
    const float* a1w  = (const float*)d_in[22];
    const float* a1b  = (const float*)d_in[23];
    const float* a2w  = (const float*)d_in[24];
    const float* a2b  = (const float*)d_in[25];

    float* out  = (float*)d_out;
    float* spk1 = out + 512;
    float* spk2 = spk1 + S1_;
    float* spk3 = spk2 + S2_;

    void *px1, *px2, *px3, *ps1, *ps2, *pw2, *pw3;
    cudaGetSymbolAddress(&px1, g_x1);
    cudaGetSymbolAddress(&px2, g_x2);
    cudaGetSymbolAddress(&px3, g_x3);
    cudaGetSymbolAddress(&ps1, g_s1h);
    cudaGetSymbolAddress(&ps2, g_s2h);
    cudaGetSymbolAddress(&pw2, g_wt2);
    cudaGetSymbolAddress(&pw3, g_wt3);
    float* x1p = (float*)px1;
    float* x2p = (float*)px2;
    float* x3p = (float*)px3;
    __half* s1h = (__half*)ps1;
    __half* s2h = (__half*)ps2;
    __half* wt2 = (__half*)pw2;
    __half* wt3 = (__half*)pw3;

    cudaFuncSetAttribute(conv_mma_kernel<C1, 4, 62, P1F, R1_, 32>,
                         cudaFuncAttributeMaxDynamicSharedMemorySize, CSMEM_BYTES);
    cudaFuncSetAttribute(conv_mma_kernel<C2, 12, 186, P2F, R2_, 64>,
                         cudaFuncAttributeMaxDynamicSharedMemorySize, CSMEM_BYTES);

    // Zero padded fp16 spike buffers (pads must be zero; interiors rewritten)
    cudaMemsetAsync(s1h, 0, (size_t)B_*R1_*C1*sizeof(__half), 0);
    cudaMemsetAsync(s2h, 0, (size_t)B_*R2_*C2*sizeof(__half), 0);

    // Weight prep (transpose + 2-limb fp16 split, lo scaled by 2048)
    wprep_kernel<<<(128*2048 + 255)/256, 256>>>(w2, wt2, 2048);
    wprep_kernel<<<(128*4096 + 255)/256, 256>>>(w3, wt3, 4096);

    // Stage 1
    conv1_bn_kernel<<<B_*T_/4, dim3(64,4)>>>(x, w1, bn1s, bn1b, bn1m, bn1v, x1p);
    hlif4_kernel<C1, R1_, P1F><<<B_*C1/4/32, 32>>>(x1p, spk1, s1h, vth1, dec1,
                                                   0.f, 1.f, 2.f, 1.f);
    // Stage 2: dilated conv (dil=4) on tensor cores (HMMA)
    conv_mma_kernel<C1, 4, 62, P1F, R1_, 32><<<dim3(8, 1, B_), 256, CSMEM_BYTES>>>(
        s1h, wt2, bn2s, bn2b, bn2m, bn2v, x2p);
    hlif4_kernel<C2, R2_, P2F><<<B_*C2/4/32, 32>>>(x2p, spk2, s2h, vth2, dec2,
                                                   0.f, 1.f, 2.f, 1.f);
    // Stage 3: dilated conv (dil=12) on tensor cores (HMMA)
    conv_mma_kernel<C2, 12, 186, P2F, R2_, 64><<<dim3(8, 1, B_), 256, CSMEM_BYTES>>>(
        s2h, wt3, bn3s, bn3b, bn3m, bn3v, x3p);
    alif4_kernel<<<B_*C3/4/32, 32>>>(x3p, spk3);
    // Readout
    readout_kernel<<<B_, 256>>>(spk3, dw, db, a1w, a1b, a2w, a2b, out);
}

// round 7
// speedup vs baseline: 1.0434x; 1.0434x over previous
#include <cuda_runtime.h>
#include <cuda_fp16.h>
#include <cstdint>
#include <math.h>

#define B_  128
#define T_  480
#define C1  64
#define C2  128
#define C3  128

#define S1_ (B_*T_*C1)
#define S2_ (B_*T_*C2)
#define S3_ (B_*T_*C3)

// Padded fp16 spike buffers (rows padded for dilated taps).
#define P1F 64
#define R1_ (P1F + T_ + 160)      // 704 rows  (conv2 max row 637)
#define P2F 192
#define R2_ (P2F + T_ + 608)      // 1280 rows (conv3 max row 889)

#define LO_SCALE 2048.0f
#define LO_INV   (1.0f/2048.0f)

// ---------------- device scratch (allocation-free) ----------------
__device__ float g_x1[S1_];
__device__ float g_x2[S2_];
__device__ float g_x3[S3_];
__device__ __align__(256) __half g_s1h[B_*R1_*C1];
__device__ __align__(256) __half g_s2h[B_*R2_*C2];
__device__ __align__(256) __half g_wt2[2*128*2048];   // [limb][o][kk]
__device__ __align__(256) __half g_wt3[2*128*4096];

// ---------------- PTX helpers (sm_80-era features only) ----------------
__device__ __forceinline__ uint32_t smem_to_u32(const void* p) {
    uint32_t a;
    asm("{ .reg .u64 t; cvta.to.shared.u64 t, %1; cvt.u32.u64 %0, t; }" : "=r"(a) : "l"(p));
    return a;
}
#define SWZ(x) ((x) ^ (((x) >> 3) & 0x70))

#define CP_ASYNC16(sa, gp) \
    asm volatile("cp.async.cg.shared.global [%0], [%1], 16;" \
        :: "r"(sa), "l"(__cvta_generic_to_global(gp)) : "memory")
#define CP_COMMIT() asm volatile("cp.async.commit_group;" ::: "memory")
#define CP_WAIT1()  asm volatile("cp.async.wait_group 1;" ::: "memory")
#define CP_WAIT0()  asm volatile("cp.async.wait_group 0;" ::: "memory")

#define LDSM_X4(r, addr) \
    asm volatile("ldmatrix.sync.aligned.m8n8.x4.shared.b16 {%0,%1,%2,%3}, [%4];" \
        : "=r"((r)[0]), "=r"((r)[1]), "=r"((r)[2]), "=r"((r)[3]) : "r"(addr))

#define MMA16816(c, a, b0, b1) \
    asm volatile("mma.sync.aligned.m16n8k16.row.col.f32.f16.f16.f32 " \
        "{%0,%1,%2,%3}, {%4,%5,%6,%7}, {%8,%9}, {%0,%1,%2,%3};" \
        : "+f"((c)[0]), "+f"((c)[1]), "+f"((c)[2]), "+f"((c)[3]) \
        : "r"((a)[0]), "r"((a)[1]), "r"((a)[2]), "r"((a)[3]), "r"(b0), "r"(b1))

// ---------------------------------------------------------------------------
// conv1 + BN1 (tiny, fp32 CUDA cores)
// ---------------------------------------------------------------------------
__global__ __launch_bounds__(256)
void conv1_bn_kernel(const float* __restrict__ x, const float* __restrict__ w1,
                     const float* __restrict__ sc, const float* __restrict__ bi,
                     const float* __restrict__ mn, const float* __restrict__ vr,
                     float* __restrict__ out) {
    __shared__ float ws[64*64];
    __shared__ float xs[4][64];
    int tid = threadIdx.y*64 + threadIdx.x;
    for (int e = tid; e < 4096; e += 256) ws[e] = w1[e];
    int row = blockIdx.x*4 + threadIdx.y;
    xs[threadIdx.y][threadIdx.x] = x[row*64 + threadIdx.x];
    __syncthreads();
    int o = threadIdx.x;
    float acc = 0.f;
    #pragma unroll 16
    for (int w = 0; w < 64; w++) acc = fmaf(xs[threadIdx.y][w], ws[w*64 + o], acc);
    float inv = rsqrtf(vr[o] + 1e-5f);
    float g = sc[o]*inv;
    out[row*64 + o] = (acc - mn[o])*g + bi[o];
}

// ---------------------------------------------------------------------------
// Weight prep: transpose + 2-limb fp16 split (lo limb scaled by 2048).
// ---------------------------------------------------------------------------
__global__ void wprep_kernel(const float* __restrict__ w, __half* __restrict__ wt,
                             int KTOT) {
    int idx = blockIdx.x*256 + threadIdx.x;
    if (idx >= 128*KTOT) return;
    int o = idx / KTOT, kk = idx % KTOT;
    float v = w[(long)kk*128 + o];
    __half hi = __float2half(v);
    __half lo = __float2half((v - __half2float(hi)) * LO_SCALE);
    wt[idx] = hi;
    wt[(long)128*KTOT + idx] = lo;
}

// ---------------------------------------------------------------------------
// HLIF scan with software prefetch of the next 8-step block (R5 version).
// ---------------------------------------------------------------------------
template<int C, int Rp, int PFp>
__global__ void hlif_kernel(const float* __restrict__ xin, float* __restrict__ spk,
                            __half* __restrict__ spkh,
                            const float* __restrict__ vth_raw,
                            const float* __restrict__ decay_raw,
                            float v_m, float v_s, float d_m, float d_s) {
    int idx = blockIdx.x*blockDim.x + threadIdx.x;
    int b = idx / C, c = idx % C;
    float vth = log1pf(expf(vth_raw[c]*v_s + v_m)) + 0.5f;
    float decay = fminf(1.f/(1.f + expf(-(decay_raw[c]*d_s + d_m))), 0.99f);
    long base = (long)b*T_*C + c;
    long bb   = ((long)b*Rp + PFp)*C + c;
    float v = 0.f;
    float xv[8], xn[8];
    #pragma unroll
    for (int j = 0; j < 8; j++) xv[j] = xin[base + (long)j*C];
    for (int t = 0; t < T_; t += 8) {
        if (t + 8 < T_) {
            #pragma unroll
            for (int j = 0; j < 8; j++) xn[j] = xin[base + (long)(t+8+j)*C];
        }
        #pragma unroll
        for (int j = 0; j < 8; j++) {
            v = v*decay + xv[j];
            float s = (v - vth) > 0.f ? 1.f : 0.f;
            v -= s*vth;
            spk[base + (long)(t+j)*C] = s;
            spkh[bb + (long)(t+j)*C] = __float2half(s);
        }
        #pragma unroll
        for (int j = 0; j < 8; j++) xv[j] = xn[j];
    }
}

// ---------------------------------------------------------------------------
// ALIF scan with software prefetch (R5 version).
// ---------------------------------------------------------------------------
__global__ void alif_kernel(const float* __restrict__ xin, float* __restrict__ spk) {
    const float d = 0.9f, adp = 0.9f, beta = 1.8f;
    int idx = blockIdx.x*blockDim.x + threadIdx.x;
    int b = idx / C3, c = idx % C3;
    long base = (long)b*T_*C3 + c;
    float v = 0.f, th = 0.f, ps = 0.f;
    float xv[8], xn[8];
    #pragma unroll
    for (int j = 0; j < 8; j++) xv[j] = xin[base + (long)j*C3];
    for (int t = 0; t < T_; t += 8) {
        if (t + 8 < T_) {
            #pragma unroll
            for (int j = 0; j < 8; j++) xn[j] = xin[base + (long)(t+8+j)*C3];
        }
        #pragma unroll
        for (int j = 0; j < 8; j++) {
            th = th*adp + ps*beta;
            v  = v*d + xv[j];
            float vt = 0.5f + th;
            float s = (v - vt) > 0.f ? 1.f : 0.f;
            v -= s*vt;
            ps = s;
            spk[base + (long)(t+j)*C3] = s;
        }
        #pragma unroll
        for (int j = 0; j < 8; j++) xv[j] = xn[j];
    }
}

// ---------------------------------------------------------------------------
// HMMA dilated conv + BN. 3-stage cp.async pipeline, 1 sync/iter.
// grid (4 m-tiles, 1, B). CTA tile 128(t) x 128(cout). K chunks of 64.
// 8 warps in 2(M) x 4(N); warp tile 64 x 32 (cuts LDSM traffic 20% vs 4x2).
// Hi/lo fp16 limbs -> separate fp32 accumulators; combined in the epilogue.
// Stage = A(16KB) + Bhi(16KB) + Blo(16KB) = 48KB; x3 stages = 144KB dynamic.
// ---------------------------------------------------------------------------
#define STAGE_BYTES 49152
#define CSMEM_BYTES (3*STAGE_BYTES)

template<int CIN, int DIL, int PADL, int PF, int Rp, int NITER>
__global__ __launch_bounds__(256)
void conv_mma_kernel(const __half* __restrict__ src, const __half* __restrict__ wt,
                     const float* __restrict__ sc, const float* __restrict__ bi,
                     const float* __restrict__ mn, const float* __restrict__ vr,
                     float* __restrict__ dst) {
    constexpr int KTOT = NITER*64;
    constexpr int CHUNKS = CIN/64;
    extern __shared__ char smem[];
    __shared__ float gsm[128], hbm[128];
    const int tid = threadIdx.x, lane = tid & 31, wid = tid >> 5;
    const int warpM = wid & 1, warpN = wid >> 1;     // 2(M) x 4(N)
    const int mtile = blockIdx.x, b = blockIdx.z;

    if (tid < 128) {
        float inv = rsqrtf(vr[tid] + 1e-5f);
        float g = sc[tid]*inv;
        gsm[tid] = g;
        hbm[tid] = bi[tid] - mn[tid]*g;
    }

    const uint32_t sbase = smem_to_u32(smem);
    const __half* sb = src + (long)b*Rp*CIN;

    float accH[4][4][4] = {};    // [mf][ng][frag]
    float accL[4][4][4] = {};

    auto issue = [&](int it) {
        const uint32_t stage = sbase + (uint32_t)(it % 3)*(uint32_t)STAGE_BYTES;
        const int k  = it / CHUNKS;
        const int c0 = (it % CHUNKS)*64;
        const long arow0 = (long)(PF + mtile*128 + k*DIL - PADL);
        #pragma unroll
        for (int rep = 0; rep < 4; rep++) {
            int idx = rep*256 + tid;
            int row = idx >> 3, seg = idx & 7;
            const __half* gp = sb + (arow0 + row)*CIN + c0 + seg*8;
            CP_ASYNC16(stage + SWZ(row*128 + seg*16), gp);
        }
        #pragma unroll
        for (int limb = 0; limb < 2; limb++) {
            const __half* wp = wt + (long)limb*128*KTOT + it*64;
            #pragma unroll
            for (int rep = 0; rep < 4; rep++) {
                int idx = rep*256 + tid;
                int row = idx >> 3, seg = idx & 7;
                const __half* gp = wp + (long)row*KTOT + seg*8;
                CP_ASYNC16(stage + 16384u + (uint32_t)limb*16384u + SWZ(row*128 + seg*16), gp);
            }
        }
        CP_COMMIT();
    };

    issue(0);
    issue(1);
    __syncthreads();  // covers gsm/hbm writes too

    for (int it = 0; it < NITER; it++) {
        if (it + 2 < NITER) CP_WAIT1(); else CP_WAIT0();
        __syncthreads();
        if (it + 2 < NITER) issue(it + 2);   // slot (it+2)%3 computed at it-1: safe

        const uint32_t stage = sbase + (uint32_t)(it % 3)*(uint32_t)STAGE_BYTES;

        #pragma unroll
        for (int ks = 0; ks < 4; ks++) {
            uint32_t a[4][4];
            #pragma unroll
            for (int mf = 0; mf < 4; mf++) {
                int row = warpM*64 + mf*16 + (lane & 15);
                LDSM_X4(a[mf], stage + SWZ(row*128 + ks*32 + (lane >> 4)*16));
            }
            #pragma unroll
            for (int limb = 0; limb < 2; limb++) {
                const uint32_t bbp = stage + 16384u + (uint32_t)limb*16384u;
                #pragma unroll
                for (int np = 0; np < 2; np++) {
                    int row = warpN*32 + np*16 + ((lane >> 4) << 3) + (lane & 7);
                    uint32_t q[4];
                    LDSM_X4(q, bbp + SWZ(row*128 + ks*32 + ((lane >> 3) & 1)*16));
                    if (limb == 0) {
                        #pragma unroll
                        for (int mf = 0; mf < 4; mf++) {
                            MMA16816(accH[mf][np*2],     a[mf], q[0], q[1]);
                            MMA16816(accH[mf][np*2 + 1], a[mf], q[2], q[3]);
                        }
                    } else {
                        #pragma unroll
                        for (int mf = 0; mf < 4; mf++) {
                            MMA16816(accL[mf][np*2],     a[mf], q[0], q[1]);
                            MMA16816(accL[mf][np*2 + 1], a[mf], q[2], q[3]);
                        }
                    }
                }
            }
        }
    }

    // Epilogue: combine limbs, BN, write fp32 pre-activations
    #pragma unroll
    for (int mf = 0; mf < 4; mf++) {
        #pragma unroll
        for (int h = 0; h < 2; h++) {
            int t = mtile*128 + warpM*64 + mf*16 + (lane >> 2) + h*8;
            if (t < T_) {
                long dr = ((long)b*T_ + t)*128;
                #pragma unroll
                for (int ng = 0; ng < 4; ng++) {
                    int col = warpN*32 + ng*8 + (lane & 3)*2;
                    float v0 = fmaf(accL[mf][ng][h*2],     LO_INV, accH[mf][ng][h*2]);
                    float v1 = fmaf(accL[mf][ng][h*2 + 1], LO_INV, accH[mf][ng][h*2 + 1]);
                    float2 o;
                    o.x = fmaf(v0, gsm[col],   hbm[col]);
                    o.y = fmaf(v1, gsm[col+1], hbm[col+1]);
                    *(float2*)&dst[dr + col] = o;
                }
            }
        }
    }
}

// ---------------------------------------------------------------------------
// Readout: dense -> LI scan -> window diff -> attention -> logits
// ---------------------------------------------------------------------------
__global__ __launch_bounds__(256)
void readout_kernel(const float* __restrict__ spk3,
                    const float* __restrict__ dw, const float* __restrict__ db,
                    const float* __restrict__ a1w, const float* __restrict__ a1b,
                    const float* __restrict__ a2w, const float* __restrict__ a2b,
                    float* __restrict__ logits) {
    __shared__ float vseq[T_*4];
    __shared__ float dp[20*4];
    __shared__ float hsm[20*8];
    __shared__ float score[20];
    __shared__ float wsm[128*4];
    int b = blockIdx.x, tid = threadIdx.x;
    for (int e = tid; e < 512; e += 256) wsm[e] = dw[e];
    __syncthreads();
    const float* sp = spk3 + (long)b*T_*C3;
    for (int e = tid; e < T_*4; e += 256) {
        int t = e >> 2, j = e & 3;
        float accv = db[j];
        const float* row = sp + (long)t*C3;
        #pragma unroll 8
        for (int c = 0; c < 128; c++) accv = fmaf(row[c], wsm[c*4 + j], accv);
        vseq[e] = accv;
    }
    __syncthreads();
    if (tid < 4) {
        float v = 0.f;
        const float dec = 0.9f, odec = 0.1f;
        for (int t = 0; t < T_; t++) {
            v = fmaf(v, dec, vseq[t*4 + tid]*odec);
            vseq[t*4 + tid] = v;
        }
    }
    __syncthreads();
    if (tid < 80) {
        int g = tid >> 2, j = tid & 3;
        float s1 = 0.f, s2 = 0.f;
        #pragma unroll
        for (int u = 0; u < 12; u++) {
            s1 += vseq[(g*24 + u)*4 + j];
            s2 += vseq[(g*24 + 12 + u)*4 + j];
        }
        dp[g*4 + j] = (s2 - s1)*(1.f/12.f);
    }
    __syncthreads();
    if (tid < 160) {
        int g = tid >> 3, u = tid & 7;
        float a = a1b[u];
        #pragma unroll
        for (int j = 0; j < 4; j++) a = fmaf(dp[g*4 + j], a1w[j*8 + u], a);
        hsm[g*8 + u] = fmaxf(a, 0.f);
    }
    __syncthreads();
    if (tid < 20) {
        float a = a2b[0];
        #pragma unroll
        for (int u = 0; u < 8; u++) a = fmaf(hsm[tid*8 + u], a2w[u], a);
        score[tid] = a;
    }
    __syncthreads();
    if (tid < 4) {
        float m = -1e30f;
        #pragma unroll
        for (int g = 0; g < 20; g++) m = fmaxf(m, score[g]);
        float den = 0.f, accv = 0.f;
        #pragma unroll
        for (int g = 0; g < 20; g++) {
            float e = expf(score[g] - m);
            den += e;
            accv = fmaf(dp[g*4 + tid], e, accv);
        }
        logits[b*4 + tid] = accv/den;
    }
}

// ---------------------------------------------------------------------------
extern "C" void kernel_launch(void* const* d_in, const int* in_sizes, int n_in,
                              void* d_out, int out_size) {
    const float* x    = (const float*)d_in[0];
    const float* w1   = (const float*)d_in[1];
    const float* bn1s = (const float*)d_in[2];
    const float* bn1b = (const float*)d_in[3];
    const float* bn1m = (const float*)d_in[4];
    const float* bn1v = (const float*)d_in[5];
    const float* vth1 = (const float*)d_in[6];
    const float* dec1 = (const float*)d_in[7];
    const float* w2   = (const float*)d_in[8];
    const float* bn2s = (const float*)d_in[9];
    const float* bn2b = (const float*)d_in[10];
    const float* bn2m = (const float*)d_in[11];
    const float* bn2v = (const float*)d_in[12];
    const float* vth2 = (const float*)d_in[13];
    const float* dec2 = (const float*)d_in[14];
    const float* w3   = (const float*)d_in[15];
    const float* bn3s = (const float*)d_in[16];
    const float* bn3b = (const float*)d_in[17];
    const float* bn3m = (const float*)d_in[18];
    const float* bn3v = (const float*)d_in[19];
    const float* dw   = (const float*)d_in[20];
    const float* db   = (const float*)d_in[21];
    const float* a1w  = (const float*)d_in[22];
    const float* a1b  = (const float*)d_in[23];
    const float* a2w  = (const float*)d_in[24];
    const float* a2b  = (const float*)d_in[25];

    float* out  = (float*)d_out;
    float* spk1 = out + 512;
    float* spk2 = spk1 + S1_;
    float* spk3 = spk2 + S2_;

    void *px1, *px2, *px3, *ps1, *ps2, *pw2, *pw3;
    cudaGetSymbolAddress(&px1, g_x1);
    cudaGetSymbolAddress(&px2, g_x2);
    cudaGetSymbolAddress(&px3, g_x3);
    cudaGetSymbolAddress(&ps1, g_s1h);
    cudaGetSymbolAddress(&ps2, g_s2h);
    cudaGetSymbolAddress(&pw2, g_wt2);
    cudaGetSymbolAddress(&pw3, g_wt3);
    float* x1p = (float*)px1;
    float* x2p = (float*)px2;
    float* x3p = (float*)px3;
    __half* s1h = (__half*)ps1;
    __half* s2h = (__half*)ps2;
    __half* wt2 = (__half*)pw2;
    __half* wt3 = (__half*)pw3;

    cudaFuncSetAttribute(conv_mma_kernel<C1, 4, 62, P1F, R1_, 32>,
                         cudaFuncAttributeMaxDynamicSharedMemorySize, CSMEM_BYTES);
    cudaFuncSetAttribute(conv_mma_kernel<C2, 12, 186, P2F, R2_, 64>,
                         cudaFuncAttributeMaxDynamicSharedMemorySize, CSMEM_BYTES);

    // Zero padded fp16 spike buffers (pads must be zero; interiors rewritten)
    cudaMemsetAsync(s1h, 0, (size_t)B_*R1_*C1*sizeof(__half), 0);
    cudaMemsetAsync(s2h, 0, (size_t)B_*R2_*C2*sizeof(__half), 0);

    // Weight prep (transpose + 2-limb fp16 split, lo scaled by 2048)
    wprep_kernel<<<(128*2048 + 255)/256, 256>>>(w2, wt2, 2048);
    wprep_kernel<<<(128*4096 + 255)/256, 256>>>(w3, wt3, 4096);

    // Stage 1
    conv1_bn_kernel<<<B_*T_/4, dim3(64,4)>>>(x, w1, bn1s, bn1b, bn1m, bn1v, x1p);
    hlif_kernel<C1, R1_, P1F><<<B_*C1/256, 256>>>(x1p, spk1, s1h, vth1, dec1,
                                                  0.f, 1.f, 2.f, 1.f);
    // Stage 2: dilated conv (dil=4) on tensor cores (HMMA)
    conv_mma_kernel<C1, 4, 62, P1F, R1_, 32><<<dim3(4, 1, B_), 256, CSMEM_BYTES>>>(
        s1h, wt2, bn2s, bn2b, bn2m, bn2v, x2p);
    hlif_kernel<C2, R2_, P2F><<<B_*C2/256, 256>>>(x2p, spk2, s2h, vth2, dec2,
                                                  0.f, 1.f, 2.f, 1.f);
    // Stage 3: dilated conv (dil=12) on tensor cores (HMMA)
    conv_mma_kernel<C2, 12, 186, P2F, R2_, 64><<<dim3(4, 1, B_), 256, CSMEM_BYTES>>>(
        s2h, wt3, bn3s, bn3b, bn3m, bn3v, x3p);
    alif_kernel<<<B_*C3/256, 256>>>(x3p, spk3);
    // Readout
    readout_kernel<<<B_, 256>>>(spk3, dw, db, a1w, a1b, a2w, a2b, out);
}

// round 8
// speedup vs baseline: 1.2361x; 1.1846x over previous
#include <cuda_runtime.h>
#include <cuda_fp16.h>
#include <cstdint>
#include <math.h>

#define B_  128
#define T_  480
#define C1  64
#define C2  128
#define C3  128

#define S1_ (B_*T_*C1)
#define S2_ (B_*T_*C2)
#define S3_ (B_*T_*C3)

// Padded fp16 spike buffers (rows padded for dilated taps).
#define P1F 64
#define R1_ (P1F + T_ + 160)      // 704 rows  (conv2 max row 637)
#define P2F 192
#define R2_ (P2F + T_ + 608)      // 1280 rows (conv3 max row 889)

#define SPK1_ELEMS ((long)B_*R1_*C1)
#define SPK2_ELEMS ((long)B_*R2_*C2)

#define LO_SCALE 2048.0f
#define LO_INV   (1.0f/2048.0f)

// ---------------- device scratch (allocation-free) ----------------
__device__ float g_x1[S1_];
__device__ float g_x2[S2_];
__device__ float g_x3[S3_];
__device__ __align__(256) __half g_spkh[SPK1_ELEMS + SPK2_ELEMS];  // one memset
__device__ __align__(256) __half g_wt2[2*128*2048];   // [limb][o][kk]
__device__ __align__(256) __half g_wt3[2*128*4096];

// ---------------- PTX helpers (sm_80-era features only) ----------------
__device__ __forceinline__ uint32_t smem_to_u32(const void* p) {
    uint32_t a;
    asm("{ .reg .u64 t; cvta.to.shared.u64 t, %1; cvt.u32.u64 %0, t; }" : "=r"(a) : "l"(p));
    return a;
}
#define SWZ(x) ((x) ^ (((x) >> 3) & 0x70))

#define CP_ASYNC16(sa, gp) \
    asm volatile("cp.async.cg.shared.global [%0], [%1], 16;" \
        :: "r"(sa), "l"(__cvta_generic_to_global(gp)) : "memory")
#define CP_COMMIT() asm volatile("cp.async.commit_group;" ::: "memory")
#define CP_WAIT1()  asm volatile("cp.async.wait_group 1;" ::: "memory")
#define CP_WAIT0()  asm volatile("cp.async.wait_group 0;" ::: "memory")

#define LDSM_X4(r, addr) \
    asm volatile("ldmatrix.sync.aligned.m8n8.x4.shared.b16 {%0,%1,%2,%3}, [%4];" \
        : "=r"((r)[0]), "=r"((r)[1]), "=r"((r)[2]), "=r"((r)[3]) : "r"(addr))

#define MMA16816(c, a, b0, b1) \
    asm volatile("mma.sync.aligned.m16n8k16.row.col.f32.f16.f16.f32 " \
        "{%0,%1,%2,%3}, {%4,%5,%6,%7}, {%8,%9}, {%0,%1,%2,%3};" \
        : "+f"((c)[0]), "+f"((c)[1]), "+f"((c)[2]), "+f"((c)[3]) \
        : "r"((a)[0]), "r"((a)[1]), "r"((a)[2]), "r"((a)[3]), "r"(b0), "r"(b1))

// ---------------------------------------------------------------------------
// conv1 + BN1 (tiny, fp32 CUDA cores)
// ---------------------------------------------------------------------------
__global__ __launch_bounds__(256)
void conv1_bn_kernel(const float* __restrict__ x, const float* __restrict__ w1,
                     const float* __restrict__ sc, const float* __restrict__ bi,
                     const float* __restrict__ mn, const float* __restrict__ vr,
                     float* __restrict__ out) {
    __shared__ float ws[64*64];
    __shared__ float xs[4][64];
    int tid = threadIdx.y*64 + threadIdx.x;
    for (int e = tid; e < 4096; e += 256) ws[e] = w1[e];
    int row = blockIdx.x*4 + threadIdx.y;
    xs[threadIdx.y][threadIdx.x] = x[row*64 + threadIdx.x];
    __syncthreads();
    int o = threadIdx.x;
    float acc = 0.f;
    #pragma unroll 16
    for (int w = 0; w < 64; w++) acc = fmaf(xs[threadIdx.y][w], ws[w*64 + o], acc);
    float inv = rsqrtf(vr[o] + 1e-5f);
    float g = sc[o]*inv;
    out[row*64 + o] = (acc - mn[o])*g + bi[o];
}

// ---------------------------------------------------------------------------
// Weight prep: transpose + 2-limb fp16 split (lo limb scaled by 2048).
// ---------------------------------------------------------------------------
__global__ void wprep_kernel(const float* __restrict__ w, __half* __restrict__ wt,
                             int KTOT) {
    int idx = blockIdx.x*256 + threadIdx.x;
    if (idx >= 128*KTOT) return;
    int o = idx / KTOT, kk = idx % KTOT;
    float v = w[(long)kk*128 + o];
    __half hi = __float2half(v);
    __half lo = __float2half((v - __half2float(hi)) * LO_SCALE);
    wt[idx] = hi;
    wt[(long)128*KTOT + idx] = lo;
}

// ---------------------------------------------------------------------------
// HLIF scan with software prefetch of the next 8-step block.
// ---------------------------------------------------------------------------
template<int C, int Rp, int PFp>
__global__ void hlif_kernel(const float* __restrict__ xin, float* __restrict__ spk,
                            __half* __restrict__ spkh,
                            const float* __restrict__ vth_raw,
                            const float* __restrict__ decay_raw,
                            float v_m, float v_s, float d_m, float d_s) {
    int idx = blockIdx.x*blockDim.x + threadIdx.x;
    int b = idx / C, c = idx % C;
    float vth = log1pf(expf(vth_raw[c]*v_s + v_m)) + 0.5f;
    float decay = fminf(1.f/(1.f + expf(-(decay_raw[c]*d_s + d_m))), 0.99f);
    long base = (long)b*T_*C + c;
    long bb   = ((long)b*Rp + PFp)*C + c;
    float v = 0.f;
    float xv[8], xn[8];
    #pragma unroll
    for (int j = 0; j < 8; j++) xv[j] = xin[base + (long)j*C];
    for (int t = 0; t < T_; t += 8) {
        if (t + 8 < T_) {
            #pragma unroll
            for (int j = 0; j < 8; j++) xn[j] = xin[base + (long)(t+8+j)*C];
        }
        #pragma unroll
        for (int j = 0; j < 8; j++) {
            v = v*decay + xv[j];
            float s = (v - vth) > 0.f ? 1.f : 0.f;
            v -= s*vth;
            spk[base + (long)(t+j)*C] = s;
            spkh[bb + (long)(t+j)*C] = __float2half(s);
        }
        #pragma unroll
        for (int j = 0; j < 8; j++) xv[j] = xn[j];
    }
}

// ---------------------------------------------------------------------------
// ALIF scan with software prefetch.
// ---------------------------------------------------------------------------
__global__ void alif_kernel(const float* __restrict__ xin, float* __restrict__ spk) {
    const float d = 0.9f, adp = 0.9f, beta = 1.8f;
    int idx = blockIdx.x*blockDim.x + threadIdx.x;
    int b = idx / C3, c = idx % C3;
    long base = (long)b*T_*C3 + c;
    float v = 0.f, th = 0.f, ps = 0.f;
    float xv[8], xn[8];
    #pragma unroll
    for (int j = 0; j < 8; j++) xv[j] = xin[base + (long)j*C3];
    for (int t = 0; t < T_; t += 8) {
        if (t + 8 < T_) {
            #pragma unroll
            for (int j = 0; j < 8; j++) xn[j] = xin[base + (long)(t+8+j)*C3];
        }
        #pragma unroll
        for (int j = 0; j < 8; j++) {
            th = th*adp + ps*beta;
            v  = v*d + xv[j];
            float vt = 0.5f + th;
            float s = (v - vt) > 0.f ? 1.f : 0.f;
            v -= s*vt;
            ps = s;
            spk[base + (long)(t+j)*C3] = s;
        }
        #pragma unroll
        for (int j = 0; j < 8; j++) xv[j] = xn[j];
    }
}

// ---------------------------------------------------------------------------
// HMMA dilated conv + BN. CTA tile 128(t) x 64(cout), 2 CTAs/SM.
// grid (4 m-tiles, 2 n-tiles, B) = 1024 CTAs (6.92 waves: no quantization).
// 8 warps in 4(M) x 2(N); warp tile 32 x 32. 3-stage cp.async pipeline.
// Hi/lo fp16 limbs -> separate fp32 accumulators (64 acc regs total).
// Stage = A(16KB) + Bhi(8KB) + Blo(8KB) = 32KB; x3 stages = 96KB dynamic.
// ---------------------------------------------------------------------------
#define STAGE_BYTES 32768
#define CSMEM_BYTES (3*STAGE_BYTES)

template<int CIN, int DIL, int PADL, int PF, int Rp, int NITER>
__global__ __launch_bounds__(256, 2)
void conv_mma_kernel(const __half* __restrict__ src, const __half* __restrict__ wt,
                     const float* __restrict__ sc, const float* __restrict__ bi,
                     const float* __restrict__ mn, const float* __restrict__ vr,
                     float* __restrict__ dst) {
    constexpr int KTOT = NITER*64;
    constexpr int CHUNKS = CIN/64;
    extern __shared__ char smem[];
    __shared__ float gsm[64], hbm[64];
    const int tid = threadIdx.x, lane = tid & 31, wid = tid >> 5;
    const int warpM = wid & 3, warpN = wid >> 2;   // 4(M) x 2(N)
    const int mtile = blockIdx.x, oBase = blockIdx.y*64, b = blockIdx.z;

    if (tid < 64) {
        int o = oBase + tid;
        float inv = rsqrtf(vr[o] + 1e-5f);
        float g = sc[o]*inv;
        gsm[tid] = g;
        hbm[tid] = bi[o] - mn[o]*g;
    }

    const uint32_t sbase = smem_to_u32(smem);
    const __half* sb = src + (long)b*Rp*CIN;

    float accH[2][4][4] = {};    // [mf][n8blk][frag]
    float accL[2][4][4] = {};

    auto issue = [&](int it) {
        const uint32_t stage = sbase + (uint32_t)(it % 3)*(uint32_t)STAGE_BYTES;
        const int k  = it / CHUNKS;
        const int c0 = (it % CHUNKS)*64;
        const long arow0 = (long)(PF + mtile*128 + k*DIL - PADL);
        #pragma unroll
        for (int rep = 0; rep < 4; rep++) {
            int idx = rep*256 + tid;
            int row = idx >> 3, seg = idx & 7;
            const __half* gp = sb + (arow0 + row)*CIN + c0 + seg*8;
            CP_ASYNC16(stage + SWZ(row*128 + seg*16), gp);
        }
        #pragma unroll
        for (int limb = 0; limb < 2; limb++) {
            const __half* wp = wt + (long)limb*128*KTOT + (long)oBase*KTOT + it*64;
            #pragma unroll
            for (int rep = 0; rep < 2; rep++) {
                int idx = rep*256 + tid;                 // 0..511
                int row = idx >> 3, seg = idx & 7;       // row 0..63
                const __half* gp = wp + (long)row*KTOT + seg*8;
                CP_ASYNC16(stage + 16384u + (uint32_t)limb*8192u + SWZ(row*128 + seg*16), gp);
            }
        }
        CP_COMMIT();
    };

    issue(0);
    issue(1);
    __syncthreads();  // covers gsm/hbm writes too

    for (int it = 0; it < NITER; it++) {
        if (it + 2 < NITER) CP_WAIT1(); else CP_WAIT0();
        __syncthreads();
        if (it + 2 < NITER) issue(it + 2);   // slot (it+2)%3 computed at it-1: safe

        const uint32_t stage = sbase + (uint32_t)(it % 3)*(uint32_t)STAGE_BYTES;

        #pragma unroll
        for (int ks = 0; ks < 4; ks++) {
            uint32_t a[2][4];
            #pragma unroll
            for (int mf = 0; mf < 2; mf++) {
                int row = warpM*32 + mf*16 + (lane & 15);
                LDSM_X4(a[mf], stage + SWZ(row*128 + ks*32 + (lane >> 4)*16));
            }
            #pragma unroll
            for (int limb = 0; limb < 2; limb++) {
                const uint32_t bbp = stage + 16384u + (uint32_t)limb*8192u;
                #pragma unroll
                for (int np = 0; np < 2; np++) {
                    int row = warpN*32 + np*16 + ((lane >> 4) << 3) + (lane & 7);
                    uint32_t q[4];
                    LDSM_X4(q, bbp + SWZ(row*128 + ks*32 + ((lane >> 3) & 1)*16));
                    if (limb == 0) {
                        #pragma unroll
                        for (int mf = 0; mf < 2; mf++) {
                            MMA16816(accH[mf][np*2],     a[mf], q[0], q[1]);
                            MMA16816(accH[mf][np*2 + 1], a[mf], q[2], q[3]);
                        }
                    } else {
                        #pragma unroll
                        for (int mf = 0; mf < 2; mf++) {
                            MMA16816(accL[mf][np*2],     a[mf], q[0], q[1]);
                            MMA16816(accL[mf][np*2 + 1], a[mf], q[2], q[3]);
                        }
                    }
                }
            }
        }
    }

    // Epilogue: combine limbs, BN, write fp32 pre-activations
    #pragma unroll
    for (int mf = 0; mf < 2; mf++) {
        #pragma unroll
        for (int h = 0; h < 2; h++) {
            int t = mtile*128 + warpM*32 + mf*16 + (lane >> 2) + h*8;
            if (t < T_) {
                long dr = ((long)b*T_ + t)*128 + oBase;
                #pragma unroll
                for (int ng = 0; ng < 4; ng++) {
                    int lc = warpN*32 + ng*8 + (lane & 3)*2;
                    float v0 = fmaf(accL[mf][ng][h*2],     LO_INV, accH[mf][ng][h*2]);
                    float v1 = fmaf(accL[mf][ng][h*2 + 1], LO_INV, accH[mf][ng][h*2 + 1]);
                    float2 o;
                    o.x = fmaf(v0, gsm[lc],   hbm[lc]);
                    o.y = fmaf(v1, gsm[lc+1], hbm[lc+1]);
                    *(float2*)&dst[dr + lc] = o;
                }
            }
        }
    }
}

// ---------------------------------------------------------------------------
// Readout: dense -> LI scan -> window diff -> attention -> logits
// ---------------------------------------------------------------------------
__global__ __launch_bounds__(256)
void readout_kernel(const float* __restrict__ spk3,
                    const float* __restrict__ dw, const float* __restrict__ db,
                    const float* __restrict__ a1w, const float* __restrict__ a1b,
                    const float* __restrict__ a2w, const float* __restrict__ a2b,
                    float* __restrict__ logits) {
    __shared__ float vseq[T_*4];
    __shared__ float dp[20*4];
    __shared__ float hsm[20*8];
    __shared__ float score[20];
    __shared__ float wsm[128*4];
    int b = blockIdx.x, tid = threadIdx.x;
    for (int e = tid; e < 512; e += 256) wsm[e] = dw[e];
    __syncthreads();
    const float* sp = spk3 + (long)b*T_*C3;
    for (int e = tid; e < T_*4; e += 256) {
        int t = e >> 2, j = e & 3;
        float accv = db[j];
        const float* row = sp + (long)t*C3;
        #pragma unroll 8
        for (int c = 0; c < 128; c++) accv = fmaf(row[c], wsm[c*4 + j], accv);
        vseq[e] = accv;
    }
    __syncthreads();
    if (tid < 4) {
        float v = 0.f;
        const float dec = 0.9f, odec = 0.1f;
        for (int t = 0; t < T_; t++) {
            v = fmaf(v, dec, vseq[t*4 + tid]*odec);
            vseq[t*4 + tid] = v;
        }
    }
    __syncthreads();
    if (tid < 80) {
        int g = tid >> 2, j = tid & 3;
        float s1 = 0.f, s2 = 0.f;
        #pragma unroll
        for (int u = 0; u < 12; u++) {
            s1 += vseq[(g*24 + u)*4 + j];
            s2 += vseq[(g*24 + 12 + u)*4 + j];
        }
        dp[g*4 + j] = (s2 - s1)*(1.f/12.f);
    }
    __syncthreads();
    if (tid < 160) {
        int g = tid >> 3, u = tid & 7;
        float a = a1b[u];
        #pragma unroll
        for (int j = 0; j < 4; j++) a = fmaf(dp[g*4 + j], a1w[j*8 + u], a);
        hsm[g*8 + u] = fmaxf(a, 0.f);
    }
    __syncthreads();
    if (tid < 20) {
        float a = a2b[0];
        #pragma unroll
        for (int u = 0; u < 8; u++) a = fmaf(hsm[tid*8 + u], a2w[u], a);
        score[tid] = a;
    }
    __syncthreads();
    if (tid < 4) {
        float m = -1e30f;
        #pragma unroll
        for (int g = 0; g < 20; g++) m = fmaxf(m, score[g]);
        float den = 0.f, accv = 0.f;
        #pragma unroll
        for (int g = 0; g < 20; g++) {
            float e = expf(score[g] - m);
            den += e;
            accv = fmaf(dp[g*4 + tid], e, accv);
        }
        logits[b*4 + tid] = accv/den;
    }
}

// ---------------------------------------------------------------------------
extern "C" void kernel_launch(void* const* d_in, const int* in_sizes, int n_in,
                              void* d_out, int out_size) {
    const float* x    = (const float*)d_in[0];
    const float* w1   = (const float*)d_in[1];
    const float* bn1s = (const float*)d_in[2];
    const float* bn1b = (const float*)d_in[3];
    const float* bn1m = (const float*)d_in[4];
    const float* bn1v = (const float*)d_in[5];
    const float* vth1 = (const float*)d_in[6];
    const float* dec1 = (const float*)d_in[7];
    const float* w2   = (const float*)d_in[8];
    const float* bn2s = (const float*)d_in[9];
    const float* bn2b = (const float*)d_in[10];
    const float* bn2m = (const float*)d_in[11];
    const float* bn2v = (const float*)d_in[12];
    const float* vth2 = (const float*)d_in[13];
    const float* dec2 = (const float*)d_in[14];
    const float* w3   = (const float*)d_in[15];
    const float* bn3s = (const float*)d_in[16];
    const float* bn3b = (const float*)d_in[17];
    const float* bn3m = (const float*)d_in[18];
    const float* bn3v = (const float*)d_in[19];
    const float* dw   = (const float*)d_in[20];
    const float* db   = (const float*)d_in[21];
    const float* a1w  = (const float*)d_in[22];
    const float* a1b  = (const float*)d_in[23];
    const float* a2w  = (const float*)d_in[24];
    const float* a2b  = (const float*)d_in[25];

    float* out  = (float*)d_out;
    float* spk1 = out + 512;
    float* spk2 = spk1 + S1_;
    float* spk3 = spk2 + S2_;

    void *px1, *px2, *px3, *psp, *pw2, *pw3;
    cudaGetSymbolAddress(&px1, g_x1);
    cudaGetSymbolAddress(&px2, g_x2);
    cudaGetSymbolAddress(&px3, g_x3);
    cudaGetSymbolAddress(&psp, g_spkh);
    cudaGetSymbolAddress(&pw2, g_wt2);
    cudaGetSymbolAddress(&pw3, g_wt3);
    float* x1p = (float*)px1;
    float* x2p = (float*)px2;
    float* x3p = (float*)px3;
    __half* s1h = (__half*)psp;
    __half* s2h = s1h + SPK1_ELEMS;
    __half* wt2 = (__half*)pw2;
    __half* wt3 = (__half*)pw3;

    cudaFuncSetAttribute(conv_mma_kernel<C1, 4, 62, P1F, R1_, 32>,
                         cudaFuncAttributeMaxDynamicSharedMemorySize, CSMEM_BYTES);
    cudaFuncSetAttribute(conv_mma_kernel<C2, 12, 186, P2F, R2_, 64>,
                         cudaFuncAttributeMaxDynamicSharedMemorySize, CSMEM_BYTES);

    // Launch 0: single memset over BOTH padded spike buffers (pads stay zero)
    cudaMemsetAsync(s1h, 0, (size_t)(SPK1_ELEMS + SPK2_ELEMS)*sizeof(__half), 0);

    // Launches 1-2: weight prep
    wprep_kernel<<<(128*2048 + 255)/256, 256>>>(w2, wt2, 2048);
    wprep_kernel<<<(128*4096 + 255)/256, 256>>>(w3, wt3, 4096);

    // Launch 3: conv1 ; 4: hlif1 ; 5: conv2 (ncu -s 5 -c 1 captures conv2)
    conv1_bn_kernel<<<B_*T_/4, dim3(64,4)>>>(x, w1, bn1s, bn1b, bn1m, bn1v, x1p);
    hlif_kernel<C1, R1_, P1F><<<B_*C1/256, 256>>>(x1p, spk1, s1h, vth1, dec1,
                                                  0.f, 1.f, 2.f, 1.f);
    conv_mma_kernel<C1, 4, 62, P1F, R1_, 32><<<dim3(4, 2, B_), 256, CSMEM_BYTES>>>(
        s1h, wt2, bn2s, bn2b, bn2m, bn2v, x2p);
    hlif_kernel<C2, R2_, P2F><<<B_*C2/256, 256>>>(x2p, spk2, s2h, vth2, dec2,
                                                  0.f, 1.f, 2.f, 1.f);
    conv_mma_kernel<C2, 12, 186, P2F, R2_, 64><<<dim3(4, 2, B_), 256, CSMEM_BYTES>>>(
        s2h, wt3, bn3s, bn3b, bn3m, bn3v, x3p);
    alif_kernel<<<B_*C3/256, 256>>>(x3p, spk3);
    readout_kernel<<<B_, 256>>>(spk3, dw, db, a1w, a1b, a2w, a2b, out);
}

// round 10
// speedup vs baseline: 1.2491x; 1.0106x over previous
#include <cuda_runtime.h>
#include <cuda_fp16.h>
#include <cstdint>
#include <math.h>

#define B_  128
#define T_  480
#define C1  64
#define C2  128
#define C3  128

#define S1_ (B_*T_*C1)
#define S2_ (B_*T_*C2)
#define S3_ (B_*T_*C3)

// Padded fp16 spike buffers (rows padded for dilated taps).
#define P1F 64
#define R1_ (P1F + T_ + 160)      // 704 rows  (conv2 max row 637)
#define P2F 192
#define R2_ (P2F + T_ + 608)      // 1280 rows (conv3 max row 889)

#define SPK1_ELEMS ((long)B_*R1_*C1)
#define SPK2_ELEMS ((long)B_*R2_*C2)

#define LO_SCALE 2048.0f
#define LO_INV   (1.0f/2048.0f)

// ---------------- device scratch (allocation-free) ----------------
__device__ float g_x1[S1_];
__device__ float g_x2[S2_];
__device__ float g_x3[S3_];
__device__ __align__(256) __half g_spkh[SPK1_ELEMS + SPK2_ELEMS];
__device__ __align__(256) __half g_wt2[2*128*2048];   // [limb][o][kk]
__device__ __align__(256) __half g_wt3[2*128*4096];

// ---------------- PTX helpers (sm_80-era features only) ----------------
__device__ __forceinline__ uint32_t smem_to_u32(const void* p) {
    uint32_t a;
    asm("{ .reg .u64 t; cvta.to.shared.u64 t, %1; cvt.u32.u64 %0, t; }" : "=r"(a) : "l"(p));
    return a;
}
#define SWZ(x) ((x) ^ (((x) >> 3) & 0x70))

#define CP_ASYNC16(sa, gp) \
    asm volatile("cp.async.cg.shared.global [%0], [%1], 16;" \
        :: "r"(sa), "l"(__cvta_generic_to_global(gp)) : "memory")
#define CP_COMMIT() asm volatile("cp.async.commit_group;" ::: "memory")
#define CP_WAIT1()  asm volatile("cp.async.wait_group 1;" ::: "memory")
#define CP_WAIT0()  asm volatile("cp.async.wait_group 0;" ::: "memory")

#define LDSM_X4(r, addr) \
    asm volatile("ldmatrix.sync.aligned.m8n8.x4.shared.b16 {%0,%1,%2,%3}, [%4];" \
        : "=r"((r)[0]), "=r"((r)[1]), "=r"((r)[2]), "=r"((r)[3]) : "r"(addr))

#define MMA16816(c, a, b0, b1) \
    asm volatile("mma.sync.aligned.m16n8k16.row.col.f32.f16.f16.f32 " \
        "{%0,%1,%2,%3}, {%4,%5,%6,%7}, {%8,%9}, {%0,%1,%2,%3};" \
        : "+f"((c)[0]), "+f"((c)[1]), "+f"((c)[2]), "+f"((c)[3]) \
        : "r"((a)[0]), "r"((a)[1]), "r"((a)[2]), "r"((a)[3]), "r"(b0), "r"(b1))

// ---------------------------------------------------------------------------
// conv1 + BN1: 8 rows/block (amortize weight smem fill), fp32 CUDA cores
// ---------------------------------------------------------------------------
__global__ __launch_bounds__(512)
void conv1_bn_kernel(const float* __restrict__ x, const float* __restrict__ w1,
                     const float* __restrict__ sc, const float* __restrict__ bi,
                     const float* __restrict__ mn, const float* __restrict__ vr,
                     float* __restrict__ out) {
    __shared__ float ws[64*64];
    __shared__ float xs[8][64];
    int tid = threadIdx.y*64 + threadIdx.x;
    for (int e = tid; e < 4096; e += 512) ws[e] = w1[e];
    int row = blockIdx.x*8 + threadIdx.y;
    xs[threadIdx.y][threadIdx.x] = x[row*64 + threadIdx.x];
    __syncthreads();
    int o = threadIdx.x;
    float acc = 0.f;
    #pragma unroll 16
    for (int w = 0; w < 64; w++) acc = fmaf(xs[threadIdx.y][w], ws[w*64 + o], acc);
    float inv = rsqrtf(vr[o] + 1e-5f);
    float g = sc[o]*inv;
    out[row*64 + o] = (acc - mn[o])*g + bi[o];
}

// ---------------------------------------------------------------------------
// Weight prep: transpose + 2-limb fp16 split (lo limb scaled by 2048).
// ---------------------------------------------------------------------------
__global__ void wprep_kernel(const float* __restrict__ w, __half* __restrict__ wt,
                             int KTOT) {
    int idx = blockIdx.x*256 + threadIdx.x;
    if (idx >= 128*KTOT) return;
    int o = idx / KTOT, kk = idx % KTOT;
    float v = w[(long)kk*128 + o];
    __half hi = __float2half(v);
    __half lo = __float2half((v - __half2float(hi)) * LO_SCALE);
    wt[idx] = hi;
    wt[(long)128*KTOT + idx] = lo;
}

// ---------------------------------------------------------------------------
// HLIF scan, block=64 for SM spread, software prefetch of next 8-step block.
// ---------------------------------------------------------------------------
template<int C, int Rp, int PFp>
__global__ __launch_bounds__(64)
void hlif_kernel(const float* __restrict__ xin, float* __restrict__ spk,
                 __half* __restrict__ spkh,
                 const float* __restrict__ vth_raw,
                 const float* __restrict__ decay_raw,
                 float v_m, float v_s, float d_m, float d_s) {
    int idx = blockIdx.x*64 + threadIdx.x;
    int b = idx / C, c = idx % C;
    float vth = log1pf(expf(vth_raw[c]*v_s + v_m)) + 0.5f;
    float decay = fminf(1.f/(1.f + expf(-(decay_raw[c]*d_s + d_m))), 0.99f);
    long base = (long)b*T_*C + c;
    long bb   = ((long)b*Rp + PFp)*C + c;
    float v = 0.f;
    float xv[8], xn[8];
    #pragma unroll
    for (int j = 0; j < 8; j++) xv[j] = xin[base + (long)j*C];
    for (int t = 0; t < T_; t += 8) {
        if (t + 8 < T_) {
            #pragma unroll
            for (int j = 0; j < 8; j++) xn[j] = xin[base + (long)(t+8+j)*C];
        }
        #pragma unroll
        for (int j = 0; j < 8; j++) {
            v = v*decay + xv[j];
            float s = (v - vth) > 0.f ? 1.f : 0.f;
            v -= s*vth;
            spk[base + (long)(t+j)*C] = s;
            spkh[bb + (long)(t+j)*C] = __float2half(s);
        }
        #pragma unroll
        for (int j = 0; j < 8; j++) xv[j] = xn[j];
    }
}

// ---------------------------------------------------------------------------
// ALIF scan, block=64, software prefetch.
// ---------------------------------------------------------------------------
__global__ __launch_bounds__(64)
void alif_kernel(const float* __restrict__ xin, float* __restrict__ spk) {
    const float d = 0.9f, adp = 0.9f, beta = 1.8f;
    int idx = blockIdx.x*64 + threadIdx.x;
    int b = idx / C3, c = idx % C3;
    long base = (long)b*T_*C3 + c;
    float v = 0.f, th = 0.f, ps = 0.f;
    float xv[8], xn[8];
    #pragma unroll
    for (int j = 0; j < 8; j++) xv[j] = xin[base + (long)j*C3];
    for (int t = 0; t < T_; t += 8) {
        if (t + 8 < T_) {
            #pragma unroll
            for (int j = 0; j < 8; j++) xn[j] = xin[base + (long)(t+8+j)*C3];
        }
        #pragma unroll
        for (int j = 0; j < 8; j++) {
            th = th*adp + ps*beta;
            v  = v*d + xv[j];
            float vt = 0.5f + th;
            float s = (v - vt) > 0.f ? 1.f : 0.f;
            v -= s*vt;
            ps = s;
            spk[base + (long)(t+j)*C3] = s;
        }
        #pragma unroll
        for (int j = 0; j < 8; j++) xv[j] = xn[j];
    }
}

// ---------------------------------------------------------------------------
// HMMA dilated conv + BN (R8 config). CTA 128(t) x 64(cout), 2 CTAs/SM,
// grid (4, 2, B) = 1024 CTAs, 3-stage cp.async, hi/lo fp16 limb accs.
// Stage = A(16KB) + Bhi(8KB) + Blo(8KB) = 32KB; x3 stages = 96KB dynamic.
// ---------------------------------------------------------------------------
#define STAGE_BYTES 32768
#define CSMEM_BYTES (3*STAGE_BYTES)

template<int CIN, int DIL, int PADL, int PF, int Rp, int NITER>
__global__ __launch_bounds__(256, 2)
void conv_mma_kernel(const __half* __restrict__ src, const __half* __restrict__ wt,
                     const float* __restrict__ sc, const float* __restrict__ bi,
                     const float* __restrict__ mn, const float* __restrict__ vr,
                     float* __restrict__ dst) {
    constexpr int KTOT = NITER*64;
    constexpr int CHUNKS = CIN/64;
    extern __shared__ char smem[];
    __shared__ float gsm[64], hbm[64];
    const int tid = threadIdx.x, lane = tid & 31, wid = tid >> 5;
    const int warpM = wid & 3, warpN = wid >> 2;   // 4(M) x 2(N)
    const int mtile = blockIdx.x, oBase = blockIdx.y*64, b = blockIdx.z;

    if (tid < 64) {
        int o = oBase + tid;
        float inv = rsqrtf(vr[o] + 1e-5f);
        float g = sc[o]*inv;
        gsm[tid] = g;
        hbm[tid] = bi[o] - mn[o]*g;
    }

    const uint32_t sbase = smem_to_u32(smem);
    const __half* sb = src + (long)b*Rp*CIN;

    float accH[2][4][4] = {};
    float accL[2][4][4] = {};

    auto issue = [&](int it) {
        const uint32_t stage = sbase + (uint32_t)(it % 3)*(uint32_t)STAGE_BYTES;
        const int k  = it / CHUNKS;
        const int c0 = (it % CHUNKS)*64;
        const long arow0 = (long)(PF + mtile*128 + k*DIL - PADL);
        #pragma unroll
        for (int rep = 0; rep < 4; rep++) {
            int idx = rep*256 + tid;
            int row = idx >> 3, seg = idx & 7;
            const __half* gp = sb + (arow0 + row)*CIN + c0 + seg*8;
            CP_ASYNC16(stage + SWZ(row*128 + seg*16), gp);
        }
        #pragma unroll
        for (int limb = 0; limb < 2; limb++) {
            const __half* wp = wt + (long)limb*128*KTOT + (long)oBase*KTOT + it*64;
            #pragma unroll
            for (int rep = 0; rep < 2; rep++) {
                int idx = rep*256 + tid;
                int row = idx >> 3, seg = idx & 7;
                const __half* gp = wp + (long)row*KTOT + seg*8;
                CP_ASYNC16(stage + 16384u + (uint32_t)limb*8192u + SWZ(row*128 + seg*16), gp);
            }
        }
        CP_COMMIT();
    };

    issue(0);
    issue(1);
    __syncthreads();

    for (int it = 0; it < NITER; it++) {
        if (it + 2 < NITER) CP_WAIT1(); else CP_WAIT0();
        __syncthreads();
        if (it + 2 < NITER) issue(it + 2);

        const uint32_t stage = sbase + (uint32_t)(it % 3)*(uint32_t)STAGE_BYTES;

        #pragma unroll
        for (int ks = 0; ks < 4; ks++) {
            uint32_t a[2][4];
            #pragma unroll
            for (int mf = 0; mf < 2; mf++) {
                int row = warpM*32 + mf*16 + (lane & 15);
                LDSM_X4(a[mf], stage + SWZ(row*128 + ks*32 + (lane >> 4)*16));
            }
            #pragma unroll
            for (int limb = 0; limb < 2; limb++) {
                const uint32_t bbp = stage + 16384u + (uint32_t)limb*8192u;
                #pragma unroll
                for (int np = 0; np < 2; np++) {
                    int row = warpN*32 + np*16 + ((lane >> 4) << 3) + (lane & 7);
                    uint32_t q[4];
                    LDSM_X4(q, bbp + SWZ(row*128 + ks*32 + ((lane >> 3) & 1)*16));
                    if (limb == 0) {
                        #pragma unroll
                        for (int mf = 0; mf < 2; mf++) {
                            MMA16816(accH[mf][np*2],     a[mf], q[0], q[1]);
                            MMA16816(accH[mf][np*2 + 1], a[mf], q[2], q[3]);
                        }
                    } else {
                        #pragma unroll
                        for (int mf = 0; mf < 2; mf++) {
                            MMA16816(accL[mf][np*2],     a[mf], q[0], q[1]);
                            MMA16816(accL[mf][np*2 + 1], a[mf], q[2], q[3]);
                        }
                    }
                }
            }
        }
    }

    #pragma unroll
    for (int mf = 0; mf < 2; mf++) {
        #pragma unroll
        for (int h = 0; h < 2; h++) {
            int t = mtile*128 + warpM*32 + mf*16 + (lane >> 2) + h*8;
            if (t < T_) {
                long dr = ((long)b*T_ + t)*128 + oBase;
                #pragma unroll
                for (int ng = 0; ng < 4; ng++) {
                    int lc = warpN*32 + ng*8 + (lane & 3)*2;
                    float v0 = fmaf(accL[mf][ng][h*2],     LO_INV, accH[mf][ng][h*2]);
                    float v1 = fmaf(accL[mf][ng][h*2 + 1], LO_INV, accH[mf][ng][h*2 + 1]);
                    float2 o;
                    o.x = fmaf(v0, gsm[lc],   hbm[lc]);
                    o.y = fmaf(v1, gsm[lc+1], hbm[lc+1]);
                    *(float2*)&dst[dr + lc] = o;
                }
            }
        }
    }
}

// ---------------------------------------------------------------------------
// Readout: dense -> LI scan -> window diff -> attention -> logits
// ---------------------------------------------------------------------------
__global__ __launch_bounds__(256)
void readout_kernel(const float* __restrict__ spk3,
                    const float* __restrict__ dw, const float* __restrict__ db,
                    const float* __restrict__ a1w, const float* __restrict__ a1b,
                    const float* __restrict__ a2w, const float* __restrict__ a2b,
                    float* __restrict__ logits) {
    __shared__ float vseq[T_*4];
    __shared__ float dp[20*4];
    __shared__ float hsm[20*8];
    __shared__ float score[20];
    __shared__ float wsm[128*4];
    int b = blockIdx.x, tid = threadIdx.x;
    for (int e = tid; e < 512; e += 256) wsm[e] = dw[e];
    __syncthreads();
    const float* sp = spk3 + (long)b*T_*C3;
    for (int e = tid; e < T_*4; e += 256) {
        int t = e >> 2, j = e & 3;
        float accv = db[j];
        const float* row = sp + (long)t*C3;
        #pragma unroll 8
        for (int c = 0; c < 128; c++) accv = fmaf(row[c], wsm[c*4 + j], accv);
        vseq[e] = accv;
    }
    __syncthreads();
    if (tid < 4) {
        float v = 0.f;
        const float dec = 0.9f, odec = 0.1f;
        for (int t = 0; t < T_; t++) {
            v = fmaf(v, dec, vseq[t*4 + tid]*odec);
            vseq[t*4 + tid] = v;
        }
    }
    __syncthreads();
    if (tid < 80) {
        int g = tid >> 2, j = tid & 3;
        float s1 = 0.f, s2 = 0.f;
        #pragma unroll
        for (int u = 0; u < 12; u++) {
            s1 += vseq[(g*24 + u)*4 + j];
            s2 += vseq[(g*24 + 12 + u)*4 + j];
        }
        dp[g*4 + j] = (s2 - s1)*(1.f/12.f);
    }
    __syncthreads();
    if (tid < 160) {
        int g = tid >> 3, u = tid & 7;
        float a = a1b[u];
        #pragma unroll
        for (int j = 0; j < 4; j++) a = fmaf(dp[g*4 + j], a1w[j*8 + u], a);
        hsm[g*8 + u] = fmaxf(a, 0.f);
    }
    __syncthreads();
    if (tid < 20) {
        float a = a2b[0];
        #pragma unroll
        for (int u = 0; u < 8; u++) a = fmaf(hsm[tid*8 + u], a2w[u], a);
        score[tid] = a;
    }
    __syncthreads();
    if (tid < 4) {
        float m = -1e30f;
        #pragma unroll
        for (int g = 0; g < 20; g++) m = fmaxf(m, score[g]);
        float den = 0.f, accv = 0.f;
        #pragma unroll
        for (int g = 0; g < 20; g++) {
            float e = expf(score[g] - m);
            den += e;
            accv = fmaf(dp[g*4 + tid], e, accv);
        }
        logits[b*4 + tid] = accv/den;
    }
}

// ---------------------------------------------------------------------------
extern "C" void kernel_launch(void* const* d_in, const int* in_sizes, int n_in,
                              void* d_out, int out_size) {
    const float* x    = (const float*)d_in[0];
    const float* w1   = (const float*)d_in[1];
    const float* bn1s = (const float*)d_in[2];
    const float* bn1b = (const float*)d_in[3];
    const float* bn1m = (const float*)d_in[4];
    const float* bn1v = (const float*)d_in[5];
    const float* vth1 = (const float*)d_in[6];
    const float* dec1 = (const float*)d_in[7];
    const float* w2   = (const float*)d_in[8];
    const float* bn2s = (const float*)d_in[9];
    const float* bn2b = (const float*)d_in[10];
    const float* bn2m = (const float*)d_in[11];
    const float* bn2v = (const float*)d_in[12];
    const float* vth2 = (const float*)d_in[13];
    const float* dec2 = (const float*)d_in[14];
    const float* w3   = (const float*)d_in[15];
    const float* bn3s = (const float*)d_in[16];
    const float* bn3b = (const float*)d_in[17];
    const float* bn3m = (const float*)d_in[18];
    const float* bn3v = (const float*)d_in[19];
    const float* dw   = (const float*)d_in[20];
    const float* db   = (const float*)d_in[21];
    const float* a1w  = (const float*)d_in[22];
    const float* a1b  = (const float*)d_in[23];
    const float* a2w  = (const float*)d_in[24];
    const float* a2b  = (const float*)d_in[25];

    float* out  = (float*)d_out;
    float* spk1 = out + 512;
    float* spk2 = spk1 + S1_;
    float* spk3 = spk2 + S2_;

    void *px1, *px2, *px3, *psp, *pw2, *pw3;
    cudaGetSymbolAddress(&px1, g_x1);
    cudaGetSymbolAddress(&px2, g_x2);
    cudaGetSymbolAddress(&px3, g_x3);
    cudaGetSymbolAddress(&psp, g_spkh);
    cudaGetSymbolAddress(&pw2, g_wt2);
    cudaGetSymbolAddress(&pw3, g_wt3);
    float* x1p = (float*)px1;
    float* x2p = (float*)px2;
    float* x3p = (float*)px3;
    __half* s1h = (__half*)psp;
    __half* s2h = s1h + SPK1_ELEMS;
    __half* wt2 = (__half*)pw2;
    __half* wt3 = (__half*)pw3;

    cudaFuncSetAttribute(conv_mma_kernel<C1, 4, 62, P1F, R1_, 32>,
                         cudaFuncAttributeMaxDynamicSharedMemorySize, CSMEM_BYTES);
    cudaFuncSetAttribute(conv_mma_kernel<C2, 12, 186, P2F, R2_, 64>,
                         cudaFuncAttributeMaxDynamicSharedMemorySize, CSMEM_BYTES);

    // Launch 0: single memset over BOTH padded spike buffers (pads stay zero)
    cudaMemsetAsync(s1h, 0, (size_t)(SPK1_ELEMS + SPK2_ELEMS)*sizeof(__half), 0);

    // Launches 1-2: weight prep
    wprep_kernel<<<(128*2048 + 255)/256, 256>>>(w2, wt2, 2048);
    wprep_kernel<<<(128*4096 + 255)/256, 256>>>(w3, wt3, 4096);

    // Launch 3: conv1 ; 4: hlif1 ; 5: conv2 (ncu -s 5 -c 1 captures conv2)
    conv1_bn_kernel<<<B_*T_/8, dim3(64,8)>>>(x, w1, bn1s, bn1b, bn1m, bn1v, x1p);
    hlif_kernel<C1, R1_, P1F><<<B_*C1/64, 64>>>(x1p, spk1, s1h, vth1, dec1,
                                                0.f, 1.f, 2.f, 1.f);
    conv_mma_kernel<C1, 4, 62, P1F, R1_, 32><<<dim3(4, 2, B_), 256, CSMEM_BYTES>>>(
        s1h, wt2, bn2s, bn2b, bn2m, bn2v, x2p);
    hlif_kernel<C2, R2_, P2F><<<B_*C2/64, 64>>>(x2p, spk2, s2h, vth2, dec2,
                                                0.f, 1.f, 2.f, 1.f);
    conv_mma_kernel<C2, 12, 186, P2F, R2_, 64><<<dim3(4, 2, B_), 256, CSMEM_BYTES>>>(
        s2h, wt3, bn3s, bn3b, bn3m, bn3v, x3p);
    alif_kernel<<<B_*C3/64, 64>>>(x3p, spk3);
    readout_kernel<<<B_, 256>>>(spk3, dw, db, a1w, a1b, a2w, a2b, out);
}

// round 11
// speedup vs baseline: 1.3050x; 1.0447x over previous
#include <cuda_runtime.h>
#include <cuda_fp16.h>
#include <cstdint>
#include <math.h>

#define B_  128
#define T_  480
#define C1  64
#define C2  128
#define C3  128

#define S1_ (B_*T_*C1)
#define S2_ (B_*T_*C2)
#define S3_ (B_*T_*C3)

// Padded fp16 spike buffers (rows padded for dilated taps).
#define P1F 64
#define R1_ (P1F + T_ + 160)      // 704 rows  (conv2 max row 637)
#define P2F 192
#define R2_ (P2F + T_ + 608)      // 1280 rows (conv3 max row 889)

#define SPK1_ELEMS ((long)B_*R1_*C1)
#define SPK2_ELEMS ((long)B_*R2_*C2)

#define LO_SCALE 2048.0f
#define LO_INV   (1.0f/2048.0f)

// ---------------- device scratch (allocation-free) ----------------
__device__ float g_x1[S1_];
__device__ float g_x2[S2_];
__device__ float g_x3[S3_];
__device__ __align__(256) __half g_spkh[SPK1_ELEMS + SPK2_ELEMS];
__device__ __align__(256) __half g_wt2[2*128*2048];   // [limb][o][kk]
__device__ __align__(256) __half g_wt3[2*128*4096];

// ---------------- PTX helpers (sm_80-era features only) ----------------
__device__ __forceinline__ uint32_t smem_to_u32(const void* p) {
    uint32_t a;
    asm("{ .reg .u64 t; cvta.to.shared.u64 t, %1; cvt.u32.u64 %0, t; }" : "=r"(a) : "l"(p));
    return a;
}
#define SWZ(x) ((x) ^ (((x) >> 3) & 0x70))

#define CP_ASYNC16(sa, gp) \
    asm volatile("cp.async.cg.shared.global [%0], [%1], 16;" \
        :: "r"(sa), "l"(__cvta_generic_to_global(gp)) : "memory")
#define CP_COMMIT() asm volatile("cp.async.commit_group;" ::: "memory")
#define CP_WAIT1()  asm volatile("cp.async.wait_group 1;" ::: "memory")
#define CP_WAIT0()  asm volatile("cp.async.wait_group 0;" ::: "memory")

#define LDSM_X4(r, addr) \
    asm volatile("ldmatrix.sync.aligned.m8n8.x4.shared.b16 {%0,%1,%2,%3}, [%4];" \
        : "=r"((r)[0]), "=r"((r)[1]), "=r"((r)[2]), "=r"((r)[3]) : "r"(addr))

#define MMA16816(c, a, b0, b1) \
    asm volatile("mma.sync.aligned.m16n8k16.row.col.f32.f16.f16.f32 " \
        "{%0,%1,%2,%3}, {%4,%5,%6,%7}, {%8,%9}, {%0,%1,%2,%3};" \
        : "+f"((c)[0]), "+f"((c)[1]), "+f"((c)[2]), "+f"((c)[3]) \
        : "r"((a)[0]), "r"((a)[1]), "r"((a)[2]), "r"((a)[3]), "r"(b0), "r"(b1))

// ---------------------------------------------------------------------------
// conv1 + BN1: 8 rows/block, fp32 CUDA cores
// ---------------------------------------------------------------------------
__global__ __launch_bounds__(512)
void conv1_bn_kernel(const float* __restrict__ x, const float* __restrict__ w1,
                     const float* __restrict__ sc, const float* __restrict__ bi,
                     const float* __restrict__ mn, const float* __restrict__ vr,
                     float* __restrict__ out) {
    __shared__ float ws[64*64];
    __shared__ float xs[8][64];
    int tid = threadIdx.y*64 + threadIdx.x;
    for (int e = tid; e < 4096; e += 512) ws[e] = w1[e];
    int row = blockIdx.x*8 + threadIdx.y;
    xs[threadIdx.y][threadIdx.x] = x[row*64 + threadIdx.x];
    __syncthreads();
    int o = threadIdx.x;
    float acc = 0.f;
    #pragma unroll 16
    for (int w = 0; w < 64; w++) acc = fmaf(xs[threadIdx.y][w], ws[w*64 + o], acc);
    float inv = rsqrtf(vr[o] + 1e-5f);
    float g = sc[o]*inv;
    out[row*64 + o] = (acc - mn[o])*g + bi[o];
}

// ---------------------------------------------------------------------------
// Weight prep: transpose + 2-limb fp16 split (lo limb scaled by 2048).
// ---------------------------------------------------------------------------
__global__ void wprep_kernel(const float* __restrict__ w, __half* __restrict__ wt,
                             int KTOT) {
    int idx = blockIdx.x*256 + threadIdx.x;
    if (idx >= 128*KTOT) return;
    int o = idx / KTOT, kk = idx % KTOT;
    float v = w[(long)kk*128 + o];
    __half hi = __float2half(v);
    __half lo = __float2half((v - __half2float(hi)) * LO_SCALE);
    wt[idx] = hi;
    wt[(long)128*KTOT + idx] = lo;
}

// ---------------------------------------------------------------------------
// HLIF scan, 16-deep software prefetch (hides DRAM latency between rounds).
// ---------------------------------------------------------------------------
template<int C, int Rp, int PFp>
__global__ __launch_bounds__(128)
void hlif_kernel(const float* __restrict__ xin, float* __restrict__ spk,
                 __half* __restrict__ spkh,
                 const float* __restrict__ vth_raw,
                 const float* __restrict__ decay_raw,
                 float v_m, float v_s, float d_m, float d_s) {
    int idx = blockIdx.x*128 + threadIdx.x;
    int b = idx / C, c = idx % C;
    float vth = log1pf(expf(vth_raw[c]*v_s + v_m)) + 0.5f;
    float decay = fminf(1.f/(1.f + expf(-(decay_raw[c]*d_s + d_m))), 0.99f);
    long base = (long)b*T_*C + c;
    long bb   = ((long)b*Rp + PFp)*C + c;
    float v = 0.f;
    float xv[16], xn[16];
    #pragma unroll
    for (int j = 0; j < 16; j++) xv[j] = xin[base + (long)j*C];
    for (int t = 0; t < T_; t += 16) {
        if (t + 16 < T_) {
            #pragma unroll
            for (int j = 0; j < 16; j++) xn[j] = xin[base + (long)(t+16+j)*C];
        }
        #pragma unroll
        for (int j = 0; j < 16; j++) {
            v = v*decay + xv[j];
            float s = (v - vth) > 0.f ? 1.f : 0.f;
            v -= s*vth;
            spk[base + (long)(t+j)*C] = s;
            spkh[bb + (long)(t+j)*C] = __float2half(s);
        }
        #pragma unroll
        for (int j = 0; j < 16; j++) xv[j] = xn[j];
    }
}

// ---------------------------------------------------------------------------
// ALIF scan, 16-deep software prefetch.
// ---------------------------------------------------------------------------
__global__ __launch_bounds__(128)
void alif_kernel(const float* __restrict__ xin, float* __restrict__ spk) {
    const float d = 0.9f, adp = 0.9f, beta = 1.8f;
    int idx = blockIdx.x*128 + threadIdx.x;
    int b = idx / C3, c = idx % C3;
    long base = (long)b*T_*C3 + c;
    float v = 0.f, th = 0.f, ps = 0.f;
    float xv[16], xn[16];
    #pragma unroll
    for (int j = 0; j < 16; j++) xv[j] = xin[base + (long)j*C3];
    for (int t = 0; t < T_; t += 16) {
        if (t + 16 < T_) {
            #pragma unroll
            for (int j = 0; j < 16; j++) xn[j] = xin[base + (long)(t+16+j)*C3];
        }
        #pragma unroll
        for (int j = 0; j < 16; j++) {
            th = th*adp + ps*beta;
            v  = v*d + xv[j];
            float vt = 0.5f + th;
            float s = (v - vt) > 0.f ? 1.f : 0.f;
            v -= s*vt;
            ps = s;
            spk[base + (long)(t+j)*C3] = s;
        }
        #pragma unroll
        for (int j = 0; j < 16; j++) xv[j] = xn[j];
    }
}

// ---------------------------------------------------------------------------
// HMMA dilated conv + BN (R8/R10 config). CTA 128(t) x 64(cout), 2 CTAs/SM,
// grid (4, 2, B) = 1024 CTAs, 3-stage cp.async, hi/lo fp16 limb accs.
// Stage = A(16KB) + Bhi(8KB) + Blo(8KB) = 32KB; x3 stages = 96KB dynamic.
// ---------------------------------------------------------------------------
#define STAGE_BYTES 32768
#define CSMEM_BYTES (3*STAGE_BYTES)

template<int CIN, int DIL, int PADL, int PF, int Rp, int NITER>
__global__ __launch_bounds__(256, 2)
void conv_mma_kernel(const __half* __restrict__ src, const __half* __restrict__ wt,
                     const float* __restrict__ sc, const float* __restrict__ bi,
                     const float* __restrict__ mn, const float* __restrict__ vr,
                     float* __restrict__ dst) {
    constexpr int KTOT = NITER*64;
    constexpr int CHUNKS = CIN/64;
    extern __shared__ char smem[];
    __shared__ float gsm[64], hbm[64];
    const int tid = threadIdx.x, lane = tid & 31, wid = tid >> 5;
    const int warpM = wid & 3, warpN = wid >> 2;   // 4(M) x 2(N)
    const int mtile = blockIdx.x, oBase = blockIdx.y*64, b = blockIdx.z;

    if (tid < 64) {
        int o = oBase + tid;
        float inv = rsqrtf(vr[o] + 1e-5f);
        float g = sc[o]*inv;
        gsm[tid] = g;
        hbm[tid] = bi[o] - mn[o]*g;
    }

    const uint32_t sbase = smem_to_u32(smem);
    const __half* sb = src + (long)b*Rp*CIN;

    float accH[2][4][4] = {};
    float accL[2][4][4] = {};

    auto issue = [&](int it) {
        const uint32_t stage = sbase + (uint32_t)(it % 3)*(uint32_t)STAGE_BYTES;
        const int k  = it / CHUNKS;
        const int c0 = (it % CHUNKS)*64;
        const long arow0 = (long)(PF + mtile*128 + k*DIL - PADL);
        #pragma unroll
        for (int rep = 0; rep < 4; rep++) {
            int idx = rep*256 + tid;
            int row = idx >> 3, seg = idx & 7;
            const __half* gp = sb + (arow0 + row)*CIN + c0 + seg*8;
            CP_ASYNC16(stage + SWZ(row*128 + seg*16), gp);
        }
        #pragma unroll
        for (int limb = 0; limb < 2; limb++) {
            const __half* wp = wt + (long)limb*128*KTOT + (long)oBase*KTOT + it*64;
            #pragma unroll
            for (int rep = 0; rep < 2; rep++) {
                int idx = rep*256 + tid;
                int row = idx >> 3, seg = idx & 7;
                const __half* gp = wp + (long)row*KTOT + seg*8;
                CP_ASYNC16(stage + 16384u + (uint32_t)limb*8192u + SWZ(row*128 + seg*16), gp);
            }
        }
        CP_COMMIT();
    };

    issue(0);
    issue(1);
    __syncthreads();

    for (int it = 0; it < NITER; it++) {
        if (it + 2 < NITER) CP_WAIT1(); else CP_WAIT0();
        __syncthreads();
        if (it + 2 < NITER) issue(it + 2);

        const uint32_t stage = sbase + (uint32_t)(it % 3)*(uint32_t)STAGE_BYTES;

        #pragma unroll
        for (int ks = 0; ks < 4; ks++) {
            uint32_t a[2][4];
            #pragma unroll
            for (int mf = 0; mf < 2; mf++) {
                int row = warpM*32 + mf*16 + (lane & 15);
                LDSM_X4(a[mf], stage + SWZ(row*128 + ks*32 + (lane >> 4)*16));
            }
            #pragma unroll
            for (int limb = 0; limb < 2; limb++) {
                const uint32_t bbp = stage + 16384u + (uint32_t)limb*8192u;
                #pragma unroll
                for (int np = 0; np < 2; np++) {
                    int row = warpN*32 + np*16 + ((lane >> 4) << 3) + (lane & 7);
                    uint32_t q[4];
                    LDSM_X4(q, bbp + SWZ(row*128 + ks*32 + ((lane >> 3) & 1)*16));
                    if (limb == 0) {
                        #pragma unroll
                        for (int mf = 0; mf < 2; mf++) {
                            MMA16816(accH[mf][np*2],     a[mf], q[0], q[1]);
                            MMA16816(accH[mf][np*2 + 1], a[mf], q[2], q[3]);
                        }
                    } else {
                        #pragma unroll
                        for (int mf = 0; mf < 2; mf++) {
                            MMA16816(accL[mf][np*2],     a[mf], q[0], q[1]);
                            MMA16816(accL[mf][np*2 + 1], a[mf], q[2], q[3]);
                        }
                    }
                }
            }
        }
    }

    #pragma unroll
    for (int mf = 0; mf < 2; mf++) {
        #pragma unroll
        for (int h = 0; h < 2; h++) {
            int t = mtile*128 + warpM*32 + mf*16 + (lane >> 2) + h*8;
            if (t < T_) {
                long dr = ((long)b*T_ + t)*128 + oBase;
                #pragma unroll
                for (int ng = 0; ng < 4; ng++) {
                    int lc = warpN*32 + ng*8 + (lane & 3)*2;
                    float v0 = fmaf(accL[mf][ng][h*2],     LO_INV, accH[mf][ng][h*2]);
                    float v1 = fmaf(accL[mf][ng][h*2 + 1], LO_INV, accH[mf][ng][h*2 + 1]);
                    float2 o;
                    o.x = fmaf(v0, gsm[lc],   hbm[lc]);
                    o.y = fmaf(v1, gsm[lc+1], hbm[lc+1]);
                    *(float2*)&dst[dr + lc] = o;
                }
            }
        }
    }
}

// ---------------------------------------------------------------------------
// Readout: dense -> LI scan -> window diff -> attention -> logits
// ---------------------------------------------------------------------------
__global__ __launch_bounds__(256)
void readout_kernel(const float* __restrict__ spk3,
                    const float* __restrict__ dw, const float* __restrict__ db,
                    const float* __restrict__ a1w, const float* __restrict__ a1b,
                    const float* __restrict__ a2w, const float* __restrict__ a2b,
                    float* __restrict__ logits) {
    __shared__ float vseq[T_*4];
    __shared__ float dp[20*4];
    __shared__ float hsm[20*8];
    __shared__ float score[20];
    __shared__ float wsm[128*4];
    int b = blockIdx.x, tid = threadIdx.x;
    for (int e = tid; e < 512; e += 256) wsm[e] = dw[e];
    __syncthreads();
    const float* sp = spk3 + (long)b*T_*C3;
    for (int e = tid; e < T_*4; e += 256) {
        int t = e >> 2, j = e & 3;
        float accv = db[j];
        const float* row = sp + (long)t*C3;
        #pragma unroll 8
        for (int c = 0; c < 128; c++) accv = fmaf(row[c], wsm[c*4 + j], accv);
        vseq[e] = accv;
    }
    __syncthreads();
    if (tid < 4) {
        float v = 0.f;
        const float dec = 0.9f, odec = 0.1f;
        for (int t = 0; t < T_; t++) {
            v = fmaf(v, dec, vseq[t*4 + tid]*odec);
            vseq[t*4 + tid] = v;
        }
    }
    __syncthreads();
    if (tid < 80) {
        int g = tid >> 2, j = tid & 3;
        float s1 = 0.f, s2 = 0.f;
        #pragma unroll
        for (int u = 0; u < 12; u++) {
            s1 += vseq[(g*24 + u)*4 + j];
            s2 += vseq[(g*24 + 12 + u)*4 + j];
        }
        dp[g*4 + j] = (s2 - s1)*(1.f/12.f);
    }
    __syncthreads();
    if (tid < 160) {
        int g = tid >> 3, u = tid & 7;
        float a = a1b[u];
        #pragma unroll
        for (int j = 0; j < 4; j++) a = fmaf(dp[g*4 + j], a1w[j*8 + u], a);
        hsm[g*8 + u] = fmaxf(a, 0.f);
    }
    __syncthreads();
    if (tid < 20) {
        float a = a2b[0];
        #pragma unroll
        for (int u = 0; u < 8; u++) a = fmaf(hsm[tid*8 + u], a2w[u], a);
        score[tid] = a;
    }
    __syncthreads();
    if (tid < 4) {
        float m = -1e30f;
        #pragma unroll
        for (int g = 0; g < 20; g++) m = fmaxf(m, score[g]);
        float den = 0.f, accv = 0.f;
        #pragma unroll
        for (int g = 0; g < 20; g++) {
            float e = expf(score[g] - m);
            den += e;
            accv = fmaf(dp[g*4 + tid], e, accv);
        }
        logits[b*4 + tid] = accv/den;
    }
}

// ---------------------------------------------------------------------------
extern "C" void kernel_launch(void* const* d_in, const int* in_sizes, int n_in,
                              void* d_out, int out_size) {
    const float* x    = (const float*)d_in[0];
    const float* w1   = (const float*)d_in[1];
    const float* bn1s = (const float*)d_in[2];
    const float* bn1b = (const float*)d_in[3];
    const float* bn1m = (const float*)d_in[4];
    const float* bn1v = (const float*)d_in[5];
    const float* vth1 = (const float*)d_in[6];
    const float* dec1 = (const float*)d_in[7];
    const float* w2   = (const float*)d_in[8];
    const float* bn2s = (const float*)d_in[9];
    const float* bn2b = (const float*)d_in[10];
    const float* bn2m = (const float*)d_in[11];
    const float* bn2v = (const float*)d_in[12];
    const float* vth2 = (const float*)d_in[13];
    const float* dec2 = (const float*)d_in[14];
    const float* w3   = (const float*)d_in[15];
    const float* bn3s = (const float*)d_in[16];
    const float* bn3b = (const float*)d_in[17];
    const float* bn3m = (const float*)d_in[18];
    const float* bn3v = (const float*)d_in[19];
    const float* dw   = (const float*)d_in[20];
    const float* db   = (const float*)d_in[21];
    const float* a1w  = (const float*)d_in[22];
    const float* a1b  = (const float*)d_in[23];
    const float* a2w  = (const float*)d_in[24];
    const float* a2b  = (const float*)d_in[25];

    float* out  = (float*)d_out;
    float* spk1 = out + 512;
    float* spk2 = spk1 + S1_;
    float* spk3 = spk2 + S2_;

    void *px1, *px2, *px3, *psp, *pw2, *pw3;
    cudaGetSymbolAddress(&px1, g_x1);
    cudaGetSymbolAddress(&px2, g_x2);
    cudaGetSymbolAddress(&px3, g_x3);
    cudaGetSymbolAddress(&psp, g_spkh);
    cudaGetSymbolAddress(&pw2, g_wt2);
    cudaGetSymbolAddress(&pw3, g_wt3);
    float* x1p = (float*)px1;
    float* x2p = (float*)px2;
    float* x3p = (float*)px3;
    __half* s1h = (__half*)psp;
    __half* s2h = s1h + SPK1_ELEMS;
    __half* wt2 = (__half*)pw2;
    __half* wt3 = (__half*)pw3;

    cudaFuncSetAttribute(conv_mma_kernel<C1, 4, 62, P1F, R1_, 32>,
                         cudaFuncAttributeMaxDynamicSharedMemorySize, CSMEM_BYTES);
    cudaFuncSetAttribute(conv_mma_kernel<C2, 12, 186, P2F, R2_, 64>,
                         cudaFuncAttributeMaxDynamicSharedMemorySize, CSMEM_BYTES);

    // Single memset over BOTH padded spike buffers (pads stay zero)
    cudaMemsetAsync(s1h, 0, (size_t)(SPK1_ELEMS + SPK2_ELEMS)*sizeof(__half), 0);

    // Weight prep
    wprep_kernel<<<(128*2048 + 255)/256, 256>>>(w2, wt2, 2048);
    wprep_kernel<<<(128*4096 + 255)/256, 256>>>(w3, wt3, 4096);

    // Pipeline
    conv1_bn_kernel<<<B_*T_/8, dim3(64,8)>>>(x, w1, bn1s, bn1b, bn1m, bn1v, x1p);
    hlif_kernel<C1, R1_, P1F><<<B_*C1/128, 128>>>(x1p, spk1, s1h, vth1, dec1,
                                                  0.f, 1.f, 2.f, 1.f);
    conv_mma_kernel<C1, 4, 62, P1F, R1_, 32><<<dim3(4, 2, B_), 256, CSMEM_BYTES>>>(
        s1h, wt2, bn2s, bn2b, bn2m, bn2v, x2p);
    hlif_kernel<C2, R2_, P2F><<<B_*C2/128, 128>>>(x2p, spk2, s2h, vth2, dec2,
                                                  0.f, 1.f, 2.f, 1.f);
    conv_mma_kernel<C2, 12, 186, P2F, R2_, 64><<<dim3(4, 2, B_), 256, CSMEM_BYTES>>>(
        s2h, wt3, bn3s, bn3b, bn3m, bn3v, x3p);
    alif_kernel<<<B_*C3/128, 128>>>(x3p, spk3);
    readout_kernel<<<B_, 256>>>(spk3, dw, db, a1w, a1b, a2w, a2b, out);
}

// round 12
// speedup vs baseline: 1.3209x; 1.0122x over previous
#include <cuda_runtime.h>
#include <cuda_fp16.h>
#include <cstdint>
#include <math.h>

#define B_  128
#define T_  480
#define C1  64
#define C2  128
#define C3  128

#define S1_ (B_*T_*C1)
#define S2_ (B_*T_*C2)
#define S3_ (B_*T_*C3)

// Padded fp16 spike buffers (rows padded for dilated taps).
#define P1F 64
#define R1_ (P1F + T_ + 160)      // 704 rows  (conv2 max row 637)
#define P2F 192
#define R2_ (P2F + T_ + 608)      // 1280 rows (conv3 max row 889)

#define SPK1_ELEMS ((long)B_*R1_*C1)
#define SPK2_ELEMS ((long)B_*R2_*C2)

#define LO_SCALE 2048.0f
#define LO_INV   (1.0f/2048.0f)

// ---------------- device scratch (allocation-free) ----------------
__device__ float g_x1[S1_];
__device__ float g_x2[S2_];
__device__ float g_x3[S3_];
__device__ __align__(256) __half g_spkh[SPK1_ELEMS + SPK2_ELEMS];
__device__ __align__(256) __half g_wt2[2*128*2048];   // [limb][o][kk]
__device__ __align__(256) __half g_wt3[2*128*4096];

// ---------------- PTX helpers (sm_80-era features only) ----------------
__device__ __forceinline__ uint32_t smem_to_u32(const void* p) {
    uint32_t a;
    asm("{ .reg .u64 t; cvta.to.shared.u64 t, %1; cvt.u32.u64 %0, t; }" : "=r"(a) : "l"(p));
    return a;
}
#define SWZ(x) ((x) ^ (((x) >> 3) & 0x70))

#define CP_ASYNC16(sa, gp) \
    asm volatile("cp.async.cg.shared.global [%0], [%1], 16;" \
        :: "r"(sa), "l"(__cvta_generic_to_global(gp)) : "memory")
#define CP_COMMIT() asm volatile("cp.async.commit_group;" ::: "memory")
#define CP_WAIT1()  asm volatile("cp.async.wait_group 1;" ::: "memory")
#define CP_WAIT0()  asm volatile("cp.async.wait_group 0;" ::: "memory")

#define LDSM_X4(r, addr) \
    asm volatile("ldmatrix.sync.aligned.m8n8.x4.shared.b16 {%0,%1,%2,%3}, [%4];" \
        : "=r"((r)[0]), "=r"((r)[1]), "=r"((r)[2]), "=r"((r)[3]) : "r"(addr))

#define MMA16816(c, a, b0, b1) \
    asm volatile("mma.sync.aligned.m16n8k16.row.col.f32.f16.f16.f32 " \
        "{%0,%1,%2,%3}, {%4,%5,%6,%7}, {%8,%9}, {%0,%1,%2,%3};" \
        : "+f"((c)[0]), "+f"((c)[1]), "+f"((c)[2]), "+f"((c)[3]) \
        : "r"((a)[0]), "r"((a)[1]), "r"((a)[2]), "r"((a)[3]), "r"(b0), "r"(b1))

// ---------------------------------------------------------------------------
// conv1 + BN1: 8 rows/block, fp32 CUDA cores
// ---------------------------------------------------------------------------
__global__ __launch_bounds__(512)
void conv1_bn_kernel(const float* __restrict__ x, const float* __restrict__ w1,
                     const float* __restrict__ sc, const float* __restrict__ bi,
                     const float* __restrict__ mn, const float* __restrict__ vr,
                     float* __restrict__ out) {
    __shared__ float ws[64*64];
    __shared__ float xs[8][64];
    int tid = threadIdx.y*64 + threadIdx.x;
    for (int e = tid; e < 4096; e += 512) ws[e] = w1[e];
    int row = blockIdx.x*8 + threadIdx.y;
    xs[threadIdx.y][threadIdx.x] = x[row*64 + threadIdx.x];
    __syncthreads();
    int o = threadIdx.x;
    float acc = 0.f;
    #pragma unroll 16
    for (int w = 0; w < 64; w++) acc = fmaf(xs[threadIdx.y][w], ws[w*64 + o], acc);
    float inv = rsqrtf(vr[o] + 1e-5f);
    float g = sc[o]*inv;
    out[row*64 + o] = (acc - mn[o])*g + bi[o];
}

// ---------------------------------------------------------------------------
// Weight prep: transpose + 2-limb fp16 split (lo limb scaled by 2048).
// ---------------------------------------------------------------------------
__global__ void wprep_kernel(const float* __restrict__ w, __half* __restrict__ wt,
                             int KTOT) {
    int idx = blockIdx.x*256 + threadIdx.x;
    if (idx >= 128*KTOT) return;
    int o = idx / KTOT, kk = idx % KTOT;
    float v = w[(long)kk*128 + o];
    __half hi = __float2half(v);
    __half lo = __float2half((v - __half2float(hi)) * LO_SCALE);
    wt[idx] = hi;
    wt[(long)128*KTOT + idx] = lo;
}

// ---------------------------------------------------------------------------
// HLIF scan, 32-deep software prefetch (T_=480 = 15 rounds of 32).
// ---------------------------------------------------------------------------
template<int C, int Rp, int PFp>
__global__ __launch_bounds__(128)
void hlif_kernel(const float* __restrict__ xin, float* __restrict__ spk,
                 __half* __restrict__ spkh,
                 const float* __restrict__ vth_raw,
                 const float* __restrict__ decay_raw,
                 float v_m, float v_s, float d_m, float d_s) {
    int idx = blockIdx.x*128 + threadIdx.x;
    int b = idx / C, c = idx % C;
    float vth = log1pf(expf(vth_raw[c]*v_s + v_m)) + 0.5f;
    float decay = fminf(1.f/(1.f + expf(-(decay_raw[c]*d_s + d_m))), 0.99f);
    long base = (long)b*T_*C + c;
    long bb   = ((long)b*Rp + PFp)*C + c;
    float v = 0.f;
    float xv[32], xn[32];
    #pragma unroll
    for (int j = 0; j < 32; j++) xv[j] = xin[base + (long)j*C];
    for (int t = 0; t < T_; t += 32) {
        if (t + 32 < T_) {
            #pragma unroll
            for (int j = 0; j < 32; j++) xn[j] = xin[base + (long)(t+32+j)*C];
        }
        #pragma unroll
        for (int j = 0; j < 32; j++) {
            v = v*decay + xv[j];
            float s = (v - vth) > 0.f ? 1.f : 0.f;
            v -= s*vth;
            spk[base + (long)(t+j)*C] = s;
            spkh[bb + (long)(t+j)*C] = __float2half(s);
        }
        #pragma unroll
        for (int j = 0; j < 32; j++) xv[j] = xn[j];
    }
}

// ---------------------------------------------------------------------------
// ALIF scan, 32-deep software prefetch.
// ---------------------------------------------------------------------------
__global__ __launch_bounds__(128)
void alif_kernel(const float* __restrict__ xin, float* __restrict__ spk) {
    const float d = 0.9f, adp = 0.9f, beta = 1.8f;
    int idx = blockIdx.x*128 + threadIdx.x;
    int b = idx / C3, c = idx % C3;
    long base = (long)b*T_*C3 + c;
    float v = 0.f, th = 0.f, ps = 0.f;
    float xv[32], xn[32];
    #pragma unroll
    for (int j = 0; j < 32; j++) xv[j] = xin[base + (long)j*C3];
    for (int t = 0; t < T_; t += 32) {
        if (t + 32 < T_) {
            #pragma unroll
            for (int j = 0; j < 32; j++) xn[j] = xin[base + (long)(t+32+j)*C3];
        }
        #pragma unroll
        for (int j = 0; j < 32; j++) {
            th = th*adp + ps*beta;
            v  = v*d + xv[j];
            float vt = 0.5f + th;
            float s = (v - vt) > 0.f ? 1.f : 0.f;
            v -= s*vt;
            ps = s;
            spk[base + (long)(t+j)*C3] = s;
        }
        #pragma unroll
        for (int j = 0; j < 32; j++) xv[j] = xn[j];
    }
}

// ---------------------------------------------------------------------------
// HMMA dilated conv + BN (R8/R10 config). CTA 128(t) x 64(cout), 2 CTAs/SM,
// grid (4, 2, B) = 1024 CTAs, 3-stage cp.async, hi/lo fp16 limb accs.
// Stage = A(16KB) + Bhi(8KB) + Blo(8KB) = 32KB; x3 stages = 96KB dynamic.
// ---------------------------------------------------------------------------
#define STAGE_BYTES 32768
#define CSMEM_BYTES (3*STAGE_BYTES)

template<int CIN, int DIL, int PADL, int PF, int Rp, int NITER>
__global__ __launch_bounds__(256, 2)
void conv_mma_kernel(const __half* __restrict__ src, const __half* __restrict__ wt,
                     const float* __restrict__ sc, const float* __restrict__ bi,
                     const float* __restrict__ mn, const float* __restrict__ vr,
                     float* __restrict__ dst) {
    constexpr int KTOT = NITER*64;
    constexpr int CHUNKS = CIN/64;
    extern __shared__ char smem[];
    __shared__ float gsm[64], hbm[64];
    const int tid = threadIdx.x, lane = tid & 31, wid = tid >> 5;
    const int warpM = wid & 3, warpN = wid >> 2;   // 4(M) x 2(N)
    const int mtile = blockIdx.x, oBase = blockIdx.y*64, b = blockIdx.z;

    if (tid < 64) {
        int o = oBase + tid;
        float inv = rsqrtf(vr[o] + 1e-5f);
        float g = sc[o]*inv;
        gsm[tid] = g;
        hbm[tid] = bi[o] - mn[o]*g;
    }

    const uint32_t sbase = smem_to_u32(smem);
    const __half* sb = src + (long)b*Rp*CIN;

    float accH[2][4][4] = {};
    float accL[2][4][4] = {};

    auto issue = [&](int it) {
        const uint32_t stage = sbase + (uint32_t)(it % 3)*(uint32_t)STAGE_BYTES;
        const int k  = it / CHUNKS;
        const int c0 = (it % CHUNKS)*64;
        const long arow0 = (long)(PF + mtile*128 + k*DIL - PADL);
        #pragma unroll
        for (int rep = 0; rep < 4; rep++) {
            int idx = rep*256 + tid;
            int row = idx >> 3, seg = idx & 7;
            const __half* gp = sb + (arow0 + row)*CIN + c0 + seg*8;
            CP_ASYNC16(stage + SWZ(row*128 + seg*16), gp);
        }
        #pragma unroll
        for (int limb = 0; limb < 2; limb++) {
            const __half* wp = wt + (long)limb*128*KTOT + (long)oBase*KTOT + it*64;
            #pragma unroll
            for (int rep = 0; rep < 2; rep++) {
                int idx = rep*256 + tid;
                int row = idx >> 3, seg = idx & 7;
                const __half* gp = wp + (long)row*KTOT + seg*8;
                CP_ASYNC16(stage + 16384u + (uint32_t)limb*8192u + SWZ(row*128 + seg*16), gp);
            }
        }
        CP_COMMIT();
    };

    issue(0);
    issue(1);
    __syncthreads();

    for (int it = 0; it < NITER; it++) {
        if (it + 2 < NITER) CP_WAIT1(); else CP_WAIT0();
        __syncthreads();
        if (it + 2 < NITER) issue(it + 2);

        const uint32_t stage = sbase + (uint32_t)(it % 3)*(uint32_t)STAGE_BYTES;

        #pragma unroll
        for (int ks = 0; ks < 4; ks++) {
            uint32_t a[2][4];
            #pragma unroll
            for (int mf = 0; mf < 2; mf++) {
                int row = warpM*32 + mf*16 + (lane & 15);
                LDSM_X4(a[mf], stage + SWZ(row*128 + ks*32 + (lane >> 4)*16));
            }
            #pragma unroll
            for (int limb = 0; limb < 2; limb++) {
                const uint32_t bbp = stage + 16384u + (uint32_t)limb*8192u;
                #pragma unroll
                for (int np = 0; np < 2; np++) {
                    int row = warpN*32 + np*16 + ((lane >> 4) << 3) + (lane & 7);
                    uint32_t q[4];
                    LDSM_X4(q, bbp + SWZ(row*128 + ks*32 + ((lane >> 3) & 1)*16));
                    if (limb == 0) {
                        #pragma unroll
                        for (int mf = 0; mf < 2; mf++) {
                            MMA16816(accH[mf][np*2],     a[mf], q[0], q[1]);
                            MMA16816(accH[mf][np*2 + 1], a[mf], q[2], q[3]);
                        }
                    } else {
                        #pragma unroll
                        for (int mf = 0; mf < 2; mf++) {
                            MMA16816(accL[mf][np*2],     a[mf], q[0], q[1]);
                            MMA16816(accL[mf][np*2 + 1], a[mf], q[2], q[3]);
                        }
                    }
                }
            }
        }
    }

    #pragma unroll
    for (int mf = 0; mf < 2; mf++) {
        #pragma unroll
        for (int h = 0; h < 2; h++) {
            int t = mtile*128 + warpM*32 + mf*16 + (lane >> 2) + h*8;
            if (t < T_) {
                long dr = ((long)b*T_ + t)*128 + oBase;
                #pragma unroll
                for (int ng = 0; ng < 4; ng++) {
                    int lc = warpN*32 + ng*8 + (lane & 3)*2;
                    float v0 = fmaf(accL[mf][ng][h*2],     LO_INV, accH[mf][ng][h*2]);
                    float v1 = fmaf(accL[mf][ng][h*2 + 1], LO_INV, accH[mf][ng][h*2 + 1]);
                    float2 o;
                    o.x = fmaf(v0, gsm[lc],   hbm[lc]);
                    o.y = fmaf(v1, gsm[lc+1], hbm[lc+1]);
                    *(float2*)&dst[dr + lc] = o;
                }
            }
        }
    }
}

// ---------------------------------------------------------------------------
// Readout: dense -> LI scan -> window diff -> attention -> logits
// ---------------------------------------------------------------------------
__global__ __launch_bounds__(256)
void readout_kernel(const float* __restrict__ spk3,
                    const float* __restrict__ dw, const float* __restrict__ db,
                    const float* __restrict__ a1w, const float* __restrict__ a1b,
                    const float* __restrict__ a2w, const float* __restrict__ a2b,
                    float* __restrict__ logits) {
    __shared__ float vseq[T_*4];
    __shared__ float dp[20*4];
    __shared__ float hsm[20*8];
    __shared__ float score[20];
    __shared__ float wsm[128*4];
    int b = blockIdx.x, tid = threadIdx.x;
    for (int e = tid; e < 512; e += 256) wsm[e] = dw[e];
    __syncthreads();
    const float* sp = spk3 + (long)b*T_*C3;
    for (int e = tid; e < T_*4; e += 256) {
        int t = e >> 2, j = e & 3;
        float accv = db[j];
        const float* row = sp + (long)t*C3;
        #pragma unroll 8
        for (int c = 0; c < 128; c++) accv = fmaf(row[c], wsm[c*4 + j], accv);
        vseq[e] = accv;
    }
    __syncthreads();
    if (tid < 4) {
        float v = 0.f;
        const float dec = 0.9f, odec = 0.1f;
        for (int t = 0; t < T_; t++) {
            v = fmaf(v, dec, vseq[t*4 + tid]*odec);
            vseq[t*4 + tid] = v;
        }
    }
    __syncthreads();
    if (tid < 80) {
        int g = tid >> 2, j = tid & 3;
        float s1 = 0.f, s2 = 0.f;
        #pragma unroll
        for (int u = 0; u < 12; u++) {
            s1 += vseq[(g*24 + u)*4 + j];
            s2 += vseq[(g*24 + 12 + u)*4 + j];
        }
        dp[g*4 + j] = (s2 - s1)*(1.f/12.f);
    }
    __syncthreads();
    if (tid < 160) {
        int g = tid >> 3, u = tid & 7;
        float a = a1b[u];
        #pragma unroll
        for (int j = 0; j < 4; j++) a = fmaf(dp[g*4 + j], a1w[j*8 + u], a);
        hsm[g*8 + u] = fmaxf(a, 0.f);
    }
    __syncthreads();
    if (tid < 20) {
        float a = a2b[0];
        #pragma unroll
        for (int u = 0; u < 8; u++) a = fmaf(hsm[tid*8 + u], a2w[u], a);
        score[tid] = a;
    }
    __syncthreads();
    if (tid < 4) {
        float m = -1e30f;
        #pragma unroll
        for (int g = 0; g < 20; g++) m = fmaxf(m, score[g]);
        float den = 0.f, accv = 0.f;
        #pragma unroll
        for (int g = 0; g < 20; g++) {
            float e = expf(score[g] - m);
            den += e;
            accv = fmaf(dp[g*4 + tid], e, accv);
        }
        logits[b*4 + tid] = accv/den;
    }
}

// ---------------------------------------------------------------------------
extern "C" void kernel_launch(void* const* d_in, const int* in_sizes, int n_in,
                              void* d_out, int out_size) {
    const float* x    = (const float*)d_in[0];
    const float* w1   = (const float*)d_in[1];
    const float* bn1s = (const float*)d_in[2];
    const float* bn1b = (const float*)d_in[3];
    const float* bn1m = (const float*)d_in[4];
    const float* bn1v = (const float*)d_in[5];
    const float* vth1 = (const float*)d_in[6];
    const float* dec1 = (const float*)d_in[7];
    const float* w2   = (const float*)d_in[8];
    const float* bn2s = (const float*)d_in[9];
    const float* bn2b = (const float*)d_in[10];
    const float* bn2m = (const float*)d_in[11];
    const float* bn2v = (const float*)d_in[12];
    const float* vth2 = (const float*)d_in[13];
    const float* dec2 = (const float*)d_in[14];
    const float* w3   = (const float*)d_in[15];
    const float* bn3s = (const float*)d_in[16];
    const float* bn3b = (const float*)d_in[17];
    const float* bn3m = (const float*)d_in[18];
    const float* bn3v = (const float*)d_in[19];
    const float* dw   = (const float*)d_in[20];
    const float* db   = (const float*)d_in[21];
    const float* a1w  = (const float*)d_in[22];
    const float* a1b  = (const float*)d_in[23];
    const float* a2w  = (const float*)d_in[24];
    const float* a2b  = (const float*)d_in[25];

    float* out  = (float*)d_out;
    float* spk1 = out + 512;
    float* spk2 = spk1 + S1_;
    float* spk3 = spk2 + S2_;

    void *px1, *px2, *px3, *psp, *pw2, *pw3;
    cudaGetSymbolAddress(&px1, g_x1);
    cudaGetSymbolAddress(&px2, g_x2);
    cudaGetSymbolAddress(&px3, g_x3);
    cudaGetSymbolAddress(&psp, g_spkh);
    cudaGetSymbolAddress(&pw2, g_wt2);
    cudaGetSymbolAddress(&pw3, g_wt3);
    float* x1p = (float*)px1;
    float* x2p = (float*)px2;
    float* x3p = (float*)px3;
    __half* s1h = (__half*)psp;
    __half* s2h = s1h + SPK1_ELEMS;
    __half* wt2 = (__half*)pw2;
    __half* wt3 = (__half*)pw3;

    cudaFuncSetAttribute(conv_mma_kernel<C1, 4, 62, P1F, R1_, 32>,
                         cudaFuncAttributeMaxDynamicSharedMemorySize, CSMEM_BYTES);
    cudaFuncSetAttribute(conv_mma_kernel<C2, 12, 186, P2F, R2_, 64>,
                         cudaFuncAttributeMaxDynamicSharedMemorySize, CSMEM_BYTES);

    // Single memset over BOTH padded spike buffers (pads stay zero)
    cudaMemsetAsync(s1h, 0, (size_t)(SPK1_ELEMS + SPK2_ELEMS)*sizeof(__half), 0);

    // Weight prep
    wprep_kernel<<<(128*2048 + 255)/256, 256>>>(w2, wt2, 2048);
    wprep_kernel<<<(128*4096 + 255)/256, 256>>>(w3, wt3, 4096);

    // Pipeline
    conv1_bn_kernel<<<B_*T_/8, dim3(64,8)>>>(x, w1, bn1s, bn1b, bn1m, bn1v, x1p);
    hlif_kernel<C1, R1_, P1F><<<B_*C1/128, 128>>>(x1p, spk1, s1h, vth1, dec1,
                                                  0.f, 1.f, 2.f, 1.f);
    conv_mma_kernel<C1, 4, 62, P1F, R1_, 32><<<dim3(4, 2, B_), 256, CSMEM_BYTES>>>(
        s1h, wt2, bn2s, bn2b, bn2m, bn2v, x2p);
    hlif_kernel<C2, R2_, P2F><<<B_*C2/128, 128>>>(x2p, spk2, s2h, vth2, dec2,
                                                  0.f, 1.f, 2.f, 1.f);
    conv_mma_kernel<C2, 12, 186, P2F, R2_, 64><<<dim3(4, 2, B_), 256, CSMEM_BYTES>>>(
        s2h, wt3, bn3s, bn3b, bn3m, bn3v, x3p);
    alif_kernel<<<B_*C3/128, 128>>>(x3p, spk3);
    readout_kernel<<<B_, 256>>>(spk3, dw, db, a1w, a1b, a2w, a2b, out);
}

// round 13
// speedup vs baseline: 1.3366x; 1.0119x over previous
#include <cuda_runtime.h>
#include <cuda_fp16.h>
#include <cstdint>
#include <math.h>

#define B_  128
#define T_  480
#define C1  64
#define C2  128
#define C3  128

#define S1_ (B_*T_*C1)
#define S2_ (B_*T_*C2)
#define S3_ (B_*T_*C3)

// Padded fp16 spike buffers (rows padded for dilated taps).
#define P1F 64
#define R1_ (P1F + T_ + 160)      // 704 rows  (conv2 max row 637)
#define P2F 192
#define R2_ (P2F + T_ + 608)      // 1280 rows (conv3 max row 889)

#define SPK1_ELEMS ((long)B_*R1_*C1)
#define SPK2_ELEMS ((long)B_*R2_*C2)

#define LO_SCALE 2048.0f
#define LO_INV   (1.0f/2048.0f)

// ---------------- device scratch (allocation-free) ----------------
// NOTE: __device__ globals are zero-initialized at module load (.bss).
// The pad rows of g_spkh are never written by any kernel, so they remain
// zero across every call/replay — no runtime memset is needed.
__device__ float g_x1[S1_];
__device__ float g_x2[S2_];
__device__ float g_x3[S3_];
__device__ __align__(256) __half g_spkh[SPK1_ELEMS + SPK2_ELEMS];
__device__ __align__(256) __half g_wt2[2*128*2048];   // [limb][o][kk]
__device__ __align__(256) __half g_wt3[2*128*4096];

// ---------------- PTX helpers (sm_80-era features only) ----------------
__device__ __forceinline__ uint32_t smem_to_u32(const void* p) {
    uint32_t a;
    asm("{ .reg .u64 t; cvta.to.shared.u64 t, %1; cvt.u32.u64 %0, t; }" : "=r"(a) : "l"(p));
    return a;
}
#define SWZ(x) ((x) ^ (((x) >> 3) & 0x70))

#define CP_ASYNC16(sa, gp) \
    asm volatile("cp.async.cg.shared.global [%0], [%1], 16;" \
        :: "r"(sa), "l"(__cvta_generic_to_global(gp)) : "memory")
#define CP_COMMIT() asm volatile("cp.async.commit_group;" ::: "memory")
#define CP_WAIT1()  asm volatile("cp.async.wait_group 1;" ::: "memory")
#define CP_WAIT0()  asm volatile("cp.async.wait_group 0;" ::: "memory")

#define LDSM_X4(r, addr) \
    asm volatile("ldmatrix.sync.aligned.m8n8.x4.shared.b16 {%0,%1,%2,%3}, [%4];" \
        : "=r"((r)[0]), "=r"((r)[1]), "=r"((r)[2]), "=r"((r)[3]) : "r"(addr))

#define MMA16816(c, a, b0, b1) \
    asm volatile("mma.sync.aligned.m16n8k16.row.col.f32.f16.f16.f32 " \
        "{%0,%1,%2,%3}, {%4,%5,%6,%7}, {%8,%9}, {%0,%1,%2,%3};" \
        : "+f"((c)[0]), "+f"((c)[1]), "+f"((c)[2]), "+f"((c)[3]) \
        : "r"((a)[0]), "r"((a)[1]), "r"((a)[2]), "r"((a)[3]), "r"(b0), "r"(b1))

// ---------------------------------------------------------------------------
// conv1 + BN1: 8 rows/block, fp32 CUDA cores
// ---------------------------------------------------------------------------
__global__ __launch_bounds__(512)
void conv1_bn_kernel(const float* __restrict__ x, const float* __restrict__ w1,
                     const float* __restrict__ sc, const float* __restrict__ bi,
                     const float* __restrict__ mn, const float* __restrict__ vr,
                     float* __restrict__ out) {
    __shared__ float ws[64*64];
    __shared__ float xs[8][64];
    int tid = threadIdx.y*64 + threadIdx.x;
    for (int e = tid; e < 4096; e += 512) ws[e] = w1[e];
    int row = blockIdx.x*8 + threadIdx.y;
    xs[threadIdx.y][threadIdx.x] = x[row*64 + threadIdx.x];
    __syncthreads();
    int o = threadIdx.x;
    float acc = 0.f;
    #pragma unroll 16
    for (int w = 0; w < 64; w++) acc = fmaf(xs[threadIdx.y][w], ws[w*64 + o], acc);
    float inv = rsqrtf(vr[o] + 1e-5f);
    float g = sc[o]*inv;
    out[row*64 + o] = (acc - mn[o])*g + bi[o];
}

// ---------------------------------------------------------------------------
// Weight prep: transpose + fp16 limb (limb 0 = hi; limb 1 = lo scaled 2048).
// LIMB selects which limb this launch writes (lets wt2 split into 2 launches
// so conv2 lands at ncu capture index 5).
// ---------------------------------------------------------------------------
template<int LIMB>
__global__ void wprep_kernel(const float* __restrict__ w, __half* __restrict__ wt,
                             int KTOT) {
    int idx = blockIdx.x*256 + threadIdx.x;
    if (idx >= 128*KTOT) return;
    int o = idx / KTOT, kk = idx % KTOT;
    float v = w[(long)kk*128 + o];
    if (LIMB == 0) {
        wt[idx] = __float2half(v);
    } else {
        __half hi = __float2half(v);
        wt[(long)128*KTOT + idx] = __float2half((v - __half2float(hi)) * LO_SCALE);
    }
}
__global__ void wprep_both_kernel(const float* __restrict__ w, __half* __restrict__ wt,
                                  int KTOT) {
    int idx = blockIdx.x*256 + threadIdx.x;
    if (idx >= 128*KTOT) return;
    int o = idx / KTOT, kk = idx % KTOT;
    float v = w[(long)kk*128 + o];
    __half hi = __float2half(v);
    wt[idx] = hi;
    wt[(long)128*KTOT + idx] = __float2half((v - __half2float(hi)) * LO_SCALE);
}

// ---------------------------------------------------------------------------
// HLIF scan, DEPTH-deep software prefetch (depth per-kernel tuned).
// ---------------------------------------------------------------------------
template<int C, int Rp, int PFp, int DEPTH>
__global__ __launch_bounds__(128)
void hlif_kernel(const float* __restrict__ xin, float* __restrict__ spk,
                 __half* __restrict__ spkh,
                 const float* __restrict__ vth_raw,
                 const float* __restrict__ decay_raw,
                 float v_m, float v_s, float d_m, float d_s) {
    int idx = blockIdx.x*128 + threadIdx.x;
    int b = idx / C, c = idx % C;
    float vth = log1pf(expf(vth_raw[c]*v_s + v_m)) + 0.5f;
    float decay = fminf(1.f/(1.f + expf(-(decay_raw[c]*d_s + d_m))), 0.99f);
    long base = (long)b*T_*C + c;
    long bb   = ((long)b*Rp + PFp)*C + c;
    float v = 0.f;
    float xv[DEPTH], xn[DEPTH];
    #pragma unroll
    for (int j = 0; j < DEPTH; j++) xv[j] = xin[base + (long)j*C];
    for (int t = 0; t < T_; t += DEPTH) {
        if (t + DEPTH < T_) {
            #pragma unroll
            for (int j = 0; j < DEPTH; j++) xn[j] = xin[base + (long)(t+DEPTH+j)*C];
        }
        #pragma unroll
        for (int j = 0; j < DEPTH; j++) {
            v = v*decay + xv[j];
            float s = (v - vth) > 0.f ? 1.f : 0.f;
            v -= s*vth;
            spk[base + (long)(t+j)*C] = s;
            spkh[bb + (long)(t+j)*C] = __float2half(s);
        }
        #pragma unroll
        for (int j = 0; j < DEPTH; j++) xv[j] = xn[j];
    }
}

// ---------------------------------------------------------------------------
// ALIF scan, 32-deep software prefetch.
// ---------------------------------------------------------------------------
__global__ __launch_bounds__(128)
void alif_kernel(const float* __restrict__ xin, float* __restrict__ spk) {
    const float d = 0.9f, adp = 0.9f, beta = 1.8f;
    int idx = blockIdx.x*128 + threadIdx.x;
    int b = idx / C3, c = idx % C3;
    long base = (long)b*T_*C3 + c;
    float v = 0.f, th = 0.f, ps = 0.f;
    float xv[32], xn[32];
    #pragma unroll
    for (int j = 0; j < 32; j++) xv[j] = xin[base + (long)j*C3];
    for (int t = 0; t < T_; t += 32) {
        if (t + 32 < T_) {
            #pragma unroll
            for (int j = 0; j < 32; j++) xn[j] = xin[base + (long)(t+32+j)*C3];
        }
        #pragma unroll
        for (int j = 0; j < 32; j++) {
            th = th*adp + ps*beta;
            v  = v*d + xv[j];
            float vt = 0.5f + th;
            float s = (v - vt) > 0.f ? 1.f : 0.f;
            v -= s*vt;
            ps = s;
            spk[base + (long)(t+j)*C3] = s;
        }
        #pragma unroll
        for (int j = 0; j < 32; j++) xv[j] = xn[j];
    }
}

// ---------------------------------------------------------------------------
// HMMA dilated conv + BN (R8/R10 config). CTA 128(t) x 64(cout), 2 CTAs/SM,
// grid (4, 2, B) = 1024 CTAs, 3-stage cp.async, hi/lo fp16 limb accs.
// Stage = A(16KB) + Bhi(8KB) + Blo(8KB) = 32KB; x3 stages = 96KB dynamic.
// ---------------------------------------------------------------------------
#define STAGE_BYTES 32768
#define CSMEM_BYTES (3*STAGE_BYTES)

template<int CIN, int DIL, int PADL, int PF, int Rp, int NITER>
__global__ __launch_bounds__(256, 2)
void conv_mma_kernel(const __half* __restrict__ src, const __half* __restrict__ wt,
                     const float* __restrict__ sc, const float* __restrict__ bi,
                     const float* __restrict__ mn, const float* __restrict__ vr,
                     float* __restrict__ dst) {
    constexpr int KTOT = NITER*64;
    constexpr int CHUNKS = CIN/64;
    extern __shared__ char smem[];
    __shared__ float gsm[64], hbm[64];
    const int tid = threadIdx.x, lane = tid & 31, wid = tid >> 5;
    const int warpM = wid & 3, warpN = wid >> 2;   // 4(M) x 2(N)
    const int mtile = blockIdx.x, oBase = blockIdx.y*64, b = blockIdx.z;

    if (tid < 64) {
        int o = oBase + tid;
        float inv = rsqrtf(vr[o] + 1e-5f);
        float g = sc[o]*inv;
        gsm[tid] = g;
        hbm[tid] = bi[o] - mn[o]*g;
    }

    const uint32_t sbase = smem_to_u32(smem);
    const __half* sb = src + (long)b*Rp*CIN;

    float accH[2][4][4] = {};
    float accL[2][4][4] = {};

    auto issue = [&](int it) {
        const uint32_t stage = sbase + (uint32_t)(it % 3)*(uint32_t)STAGE_BYTES;
        const int k  = it / CHUNKS;
        const int c0 = (it % CHUNKS)*64;
        const long arow0 = (long)(PF + mtile*128 + k*DIL - PADL);
        #pragma unroll
        for (int rep = 0; rep < 4; rep++) {
            int idx = rep*256 + tid;
            int row = idx >> 3, seg = idx & 7;
            const __half* gp = sb + (arow0 + row)*CIN + c0 + seg*8;
            CP_ASYNC16(stage + SWZ(row*128 + seg*16), gp);
        }
        #pragma unroll
        for (int limb = 0; limb < 2; limb++) {
            const __half* wp = wt + (long)limb*128*KTOT + (long)oBase*KTOT + it*64;
            #pragma unroll
            for (int rep = 0; rep < 2; rep++) {
                int idx = rep*256 + tid;
                int row = idx >> 3, seg = idx & 7;
                const __half* gp = wp + (long)row*KTOT + seg*8;
                CP_ASYNC16(stage + 16384u + (uint32_t)limb*8192u + SWZ(row*128 + seg*16), gp);
            }
        }
        CP_COMMIT();
    };

    issue(0);
    issue(1);
    __syncthreads();

    for (int it = 0; it < NITER; it++) {
        if (it + 2 < NITER) CP_WAIT1(); else CP_WAIT0();
        __syncthreads();
        if (it + 2 < NITER) issue(it + 2);

        const uint32_t stage = sbase + (uint32_t)(it % 3)*(uint32_t)STAGE_BYTES;

        #pragma unroll
        for (int ks = 0; ks < 4; ks++) {
            uint32_t a[2][4];
            #pragma unroll
            for (int mf = 0; mf < 2; mf++) {
                int row = warpM*32 + mf*16 + (lane & 15);
                LDSM_X4(a[mf], stage + SWZ(row*128 + ks*32 + (lane >> 4)*16));
            }
            #pragma unroll
            for (int limb = 0; limb < 2; limb++) {
                const uint32_t bbp = stage + 16384u + (uint32_t)limb*8192u;
                #pragma unroll
                for (int np = 0; np < 2; np++) {
                    int row = warpN*32 + np*16 + ((lane >> 4) << 3) + (lane & 7);
                    uint32_t q[4];
                    LDSM_X4(q, bbp + SWZ(row*128 + ks*32 + ((lane >> 3) & 1)*16));
                    if (limb == 0) {
                        #pragma unroll
                        for (int mf = 0; mf < 2; mf++) {
                            MMA16816(accH[mf][np*2],     a[mf], q[0], q[1]);
                            MMA16816(accH[mf][np*2 + 1], a[mf], q[2], q[3]);
                        }
                    } else {
                        #pragma unroll
                        for (int mf = 0; mf < 2; mf++) {
                            MMA16816(accL[mf][np*2],     a[mf], q[0], q[1]);
                            MMA16816(accL[mf][np*2 + 1], a[mf], q[2], q[3]);
                        }
                    }
                }
            }
        }
    }

    #pragma unroll
    for (int mf = 0; mf < 2; mf++) {
        #pragma unroll
        for (int h = 0; h < 2; h++) {
            int t = mtile*128 + warpM*32 + mf*16 + (lane >> 2) + h*8;
            if (t < T_) {
                long dr = ((long)b*T_ + t)*128 + oBase;
                #pragma unroll
                for (int ng = 0; ng < 4; ng++) {
                    int lc = warpN*32 + ng*8 + (lane & 3)*2;
                    float v0 = fmaf(accL[mf][ng][h*2],     LO_INV, accH[mf][ng][h*2]);
                    float v1 = fmaf(accL[mf][ng][h*2 + 1], LO_INV, accH[mf][ng][h*2 + 1]);
                    float2 o;
                    o.x = fmaf(v0, gsm[lc],   hbm[lc]);
                    o.y = fmaf(v1, gsm[lc+1], hbm[lc+1]);
                    *(float2*)&dst[dr + lc] = o;
                }
            }
        }
    }
}

// ---------------------------------------------------------------------------
// Readout: dense -> LI scan -> window diff -> attention -> logits
// ---------------------------------------------------------------------------
__global__ __launch_bounds__(256)
void readout_kernel(const float* __restrict__ spk3,
                    const float* __restrict__ dw, const float* __restrict__ db,
                    const float* __restrict__ a1w, const float* __restrict__ a1b,
                    const float* __restrict__ a2w, const float* __restrict__ a2b,
                    float* __restrict__ logits) {
    __shared__ float vseq[T_*4];
    __shared__ float dp[20*4];
    __shared__ float hsm[20*8];
    __shared__ float score[20];
    __shared__ float wsm[128*4];
    int b = blockIdx.x, tid = threadIdx.x;
    for (int e = tid; e < 512; e += 256) wsm[e] = dw[e];
    __syncthreads();
    const float* sp = spk3 + (long)b*T_*C3;
    for (int e = tid; e < T_*4; e += 256) {
        int t = e >> 2, j = e & 3;
        float accv = db[j];
        const float* row = sp + (long)t*C3;
        #pragma unroll 8
        for (int c = 0; c < 128; c++) accv = fmaf(row[c], wsm[c*4 + j], accv);
        vseq[e] = accv;
    }
    __syncthreads();
    if (tid < 4) {
        float v = 0.f;
        const float dec = 0.9f, odec = 0.1f;
        for (int t = 0; t < T_; t++) {
            v = fmaf(v, dec, vseq[t*4 + tid]*odec);
            vseq[t*4 + tid] = v;
        }
    }
    __syncthreads();
    if (tid < 80) {
        int g = tid >> 2, j = tid & 3;
        float s1 = 0.f, s2 = 0.f;
        #pragma unroll
        for (int u = 0; u < 12; u++) {
            s1 += vseq[(g*24 + u)*4 + j];
            s2 += vseq[(g*24 + 12 + u)*4 + j];
        }
        dp[g*4 + j] = (s2 - s1)*(1.f/12.f);
    }
    __syncthreads();
    if (tid < 160) {
        int g = tid >> 3, u = tid & 7;
        float a = a1b[u];
        #pragma unroll
        for (int j = 0; j < 4; j++) a = fmaf(dp[g*4 + j], a1w[j*8 + u], a);
        hsm[g*8 + u] = fmaxf(a, 0.f);
    }
    __syncthreads();
    if (tid < 20) {
        float a = a2b[0];
        #pragma unroll
        for (int u = 0; u < 8; u++) a = fmaf(hsm[tid*8 + u], a2w[u], a);
        score[tid] = a;
    }
    __syncthreads();
    if (tid < 4) {
        float m = -1e30f;
        #pragma unroll
        for (int g = 0; g < 20; g++) m = fmaxf(m, score[g]);
        float den = 0.f, accv = 0.f;
        #pragma unroll
        for (int g = 0; g < 20; g++) {
            float e = expf(score[g] - m);
            den += e;
            accv = fmaf(dp[g*4 + tid], e, accv);
        }
        logits[b*4 + tid] = accv/den;
    }
}

// ---------------------------------------------------------------------------
extern "C" void kernel_launch(void* const* d_in, const int* in_sizes, int n_in,
                              void* d_out, int out_size) {
    const float* x    = (const float*)d_in[0];
    const float* w1   = (const float*)d_in[1];
    const float* bn1s = (const float*)d_in[2];
    const float* bn1b = (const float*)d_in[3];
    const float* bn1m = (const float*)d_in[4];
    const float* bn1v = (const float*)d_in[5];
    const float* vth1 = (const float*)d_in[6];
    const float* dec1 = (const float*)d_in[7];
    const float* w2   = (const float*)d_in[8];
    const float* bn2s = (const float*)d_in[9];
    const float* bn2b = (const float*)d_in[10];
    const float* bn2m = (const float*)d_in[11];
    const float* bn2v = (const float*)d_in[12];
    const float* vth2 = (const float*)d_in[13];
    const float* dec2 = (const float*)d_in[14];
    const float* w3   = (const float*)d_in[15];
    const float* bn3s = (const float*)d_in[16];
    const float* bn3b = (const float*)d_in[17];
    const float* bn3m = (const float*)d_in[18];
    const float* bn3v = (const float*)d_in[19];
    const float* dw   = (const float*)d_in[20];
    const float* db   = (const float*)d_in[21];
    const float* a1w  = (const float*)d_in[22];
    const float* a1b  = (const float*)d_in[23];
    const float* a2w  = (const float*)d_in[24];
    const float* a2b  = (const float*)d_in[25];

    float* out  = (float*)d_out;
    float* spk1 = out + 512;
    float* spk2 = spk1 + S1_;
    float* spk3 = spk2 + S2_;

    void *px1, *px2, *px3, *psp, *pw2, *pw3;
    cudaGetSymbolAddress(&px1, g_x1);
    cudaGetSymbolAddress(&px2, g_x2);
    cudaGetSymbolAddress(&px3, g_x3);
    cudaGetSymbolAddress(&psp, g_spkh);
    cudaGetSymbolAddress(&pw2, g_wt2);
    cudaGetSymbolAddress(&pw3, g_wt3);
    float* x1p = (float*)px1;
    float* x2p = (float*)px2;
    float* x3p = (float*)px3;
    __half* s1h = (__half*)psp;
    __half* s2h = s1h + SPK1_ELEMS;
    __half* wt2 = (__half*)pw2;
    __half* wt3 = (__half*)pw3;

    cudaFuncSetAttribute(conv_mma_kernel<C1, 4, 62, P1F, R1_, 32>,
                         cudaFuncAttributeMaxDynamicSharedMemorySize, CSMEM_BYTES);
    cudaFuncSetAttribute(conv_mma_kernel<C2, 12, 186, P2F, R2_, 64>,
                         cudaFuncAttributeMaxDynamicSharedMemorySize, CSMEM_BYTES);

    // No memset: g_spkh pads are .bss-zero and never written by any kernel.
    // Launch order (for ncu -s 5 -c 1 => index 5 = conv2):
    // 0: wprep2 hi, 1: wprep2 lo, 2: wprep3 both, 3: conv1, 4: hlif1, 5: conv2
    wprep_kernel<0><<<(128*2048 + 255)/256, 256>>>(w2, wt2, 2048);
    wprep_kernel<1><<<(128*2048 + 255)/256, 256>>>(w2, wt2, 2048);
    wprep_both_kernel<<<(128*4096 + 255)/256, 256>>>(w3, wt3, 4096);

    conv1_bn_kernel<<<B_*T_/8, dim3(64,8)>>>(x, w1, bn1s, bn1b, bn1m, bn1v, x1p);
    hlif_kernel<C1, R1_, P1F, 16><<<B_*C1/128, 128>>>(x1p, spk1, s1h, vth1, dec1,
                                                      0.f, 1.f, 2.f, 1.f);
    conv_mma_kernel<C1, 4, 62, P1F, R1_, 32><<<dim3(4, 2, B_), 256, CSMEM_BYTES>>>(
        s1h, wt2, bn2s, bn2b, bn2m, bn2v, x2p);
    hlif_kernel<C2, R2_, P2F, 32><<<B_*C2/128, 128>>>(x2p, spk2, s2h, vth2, dec2,
                                                      0.f, 1.f, 2.f, 1.f);
    conv_mma_kernel<C2, 12, 186, P2F, R2_, 64><<<dim3(4, 2, B_), 256, CSMEM_BYTES>>>(
        s2h, wt3, bn3s, bn3b, bn3m, bn3v, x3p);
    alif_kernel<<<B_*C3/128, 128>>>(x3p, spk3);
    readout_kernel<<<B_, 256>>>(spk3, dw, db, a1w, a1b, a2w, a2b, out);
}

// round 14
// speedup vs baseline: 1.4246x; 1.0658x over previous
#include <cuda_runtime.h>
#include <cuda_fp16.h>
#include <cstdint>
#include <math.h>

#define B_  128
#define T_  480
#define C1  64
#define C2  128
#define C3  128

#define S1_ (B_*T_*C1)
#define S2_ (B_*T_*C2)
#define S3_ (B_*T_*C3)

// Padded fp16 spike buffers (rows padded for dilated taps).
#define P1F 64
#define R1_ (P1F + T_ + 160)      // 704 rows  (conv2 max row 637)
#define P2F 192
#define R2_ (P2F + T_ + 608)      // 1280 rows (conv3 max row 889)

#define SPK1_ELEMS ((long)B_*R1_*C1)
#define SPK2_ELEMS ((long)B_*R2_*C2)

#define LO_SCALE 2048.0f
#define LO_INV   (1.0f/2048.0f)

// ---------------- device scratch (allocation-free) ----------------
// __device__ globals are .bss zero-initialized; g_spkh pads are never
// written by any kernel, so they stay zero across replays (no memset).
__device__ float g_x1[S1_];
__device__ float g_x2[S2_];
__device__ float g_x3[S3_];
__device__ __align__(256) __half g_spkh[SPK1_ELEMS + SPK2_ELEMS];
__device__ __align__(256) __half g_wt2[2*128*2048];   // [limb][o][kk]
__device__ __align__(256) __half g_wt3[2*128*4096];

// ---------------- PTX helpers (sm_80-era features only) ----------------
__device__ __forceinline__ uint32_t smem_to_u32(const void* p) {
    uint32_t a;
    asm("{ .reg .u64 t; cvta.to.shared.u64 t, %1; cvt.u32.u64 %0, t; }" : "=r"(a) : "l"(p));
    return a;
}
#define SWZ(x) ((x) ^ (((x) >> 3) & 0x70))

#define CP_ASYNC16(sa, gp) \
    asm volatile("cp.async.cg.shared.global [%0], [%1], 16;" \
        :: "r"(sa), "l"(__cvta_generic_to_global(gp)) : "memory")
#define CP_COMMIT() asm volatile("cp.async.commit_group;" ::: "memory")
#define CP_WAIT1()  asm volatile("cp.async.wait_group 1;" ::: "memory")
#define CP_WAIT0()  asm volatile("cp.async.wait_group 0;" ::: "memory")

#define LDSM_X4(r, addr) \
    asm volatile("ldmatrix.sync.aligned.m8n8.x4.shared.b16 {%0,%1,%2,%3}, [%4];" \
        : "=r"((r)[0]), "=r"((r)[1]), "=r"((r)[2]), "=r"((r)[3]) : "r"(addr))

#define MMA16816(c, a, b0, b1) \
    asm volatile("mma.sync.aligned.m16n8k16.row.col.f32.f16.f16.f32 " \
        "{%0,%1,%2,%3}, {%4,%5,%6,%7}, {%8,%9}, {%0,%1,%2,%3};" \
        : "+f"((c)[0]), "+f"((c)[1]), "+f"((c)[2]), "+f"((c)[3]) \
        : "r"((a)[0]), "r"((a)[1]), "r"((a)[2]), "r"((a)[3]), "r"(b0), "r"(b1))

// ---------------------------------------------------------------------------
// conv1 + BN1 v2: register-tiled 64x64 GEMM per 64-row tile.
// 256 threads (16x16), 4x4 register tile, k-major smem, float4 reads.
// Inner-loop FMA order per output identical to v1 -> bitwise-same results.
// ---------------------------------------------------------------------------
__global__ __launch_bounds__(256)
void conv1_bn_kernel(const float* __restrict__ x, const float* __restrict__ w1,
                     const float* __restrict__ sc, const float* __restrict__ bi,
                     const float* __restrict__ mn, const float* __restrict__ vr,
                     float* __restrict__ out) {
    const int LDP = 68;
    __shared__ float As[64*LDP];   // As[w][tl] = x[(row0+tl)*64 + w]
    __shared__ float Bs[64*LDP];   // Bs[w][o]  = w1[w*64 + o]
    int tid = threadIdx.x;
    int tx = tid & 15, ty = tid >> 4;
    long row0 = (long)blockIdx.x*64;

    #pragma unroll
    for (int rep = 0; rep < 16; rep++) {
        int e = rep*256 + tid;          // 0..4095
        int tl = e >> 6, w = e & 63;
        As[w*LDP + tl] = x[(row0 + tl)*64 + w];
        Bs[(e >> 6)*LDP + (e & 63)] = w1[e];
    }
    __syncthreads();

    float acc[4][4];
    #pragma unroll
    for (int r = 0; r < 4; r++)
        #pragma unroll
        for (int c = 0; c < 4; c++) acc[r][c] = 0.f;

    #pragma unroll 16
    for (int w = 0; w < 64; w++) {
        float4 a4 = *(const float4*)&As[w*LDP + ty*4];
        float4 b4 = *(const float4*)&Bs[w*LDP + tx*4];
        float ar[4] = {a4.x, a4.y, a4.z, a4.w};
        float br[4] = {b4.x, b4.y, b4.z, b4.w};
        #pragma unroll
        for (int r = 0; r < 4; r++)
            #pragma unroll
            for (int c = 0; c < 4; c++)
                acc[r][c] = fmaf(ar[r], br[c], acc[r][c]);
    }

    // BN epilogue
    float gs[4], hb[4];
    #pragma unroll
    for (int c = 0; c < 4; c++) {
        int o = tx*4 + c;
        float inv = rsqrtf(vr[o] + 1e-5f);
        gs[c] = sc[o]*inv;
        hb[c] = bi[o] - mn[o]*gs[c];
    }
    #pragma unroll
    for (int r = 0; r < 4; r++) {
        long rw = (row0 + ty*4 + r)*64;
        float4 o4;
        o4.x = fmaf(acc[r][0], gs[0], hb[0]);
        o4.y = fmaf(acc[r][1], gs[1], hb[1]);
        o4.z = fmaf(acc[r][2], gs[2], hb[2]);
        o4.w = fmaf(acc[r][3], gs[3], hb[3]);
        *(float4*)&out[rw + tx*4] = o4;
    }
}

// ---------------------------------------------------------------------------
// Weight prep: transpose + fp16 limb (limb 0 = hi; limb 1 = lo scaled 2048).
// ---------------------------------------------------------------------------
template<int LIMB>
__global__ void wprep_kernel(const float* __restrict__ w, __half* __restrict__ wt,
                             int KTOT) {
    int idx = blockIdx.x*256 + threadIdx.x;
    if (idx >= 128*KTOT) return;
    int o = idx / KTOT, kk = idx % KTOT;
    float v = w[(long)kk*128 + o];
    if (LIMB == 0) {
        wt[idx] = __float2half(v);
    } else {
        __half hi = __float2half(v);
        wt[(long)128*KTOT + idx] = __float2half((v - __half2float(hi)) * LO_SCALE);
    }
}
__global__ void wprep_both_kernel(const float* __restrict__ w, __half* __restrict__ wt,
                                  int KTOT) {
    int idx = blockIdx.x*256 + threadIdx.x;
    if (idx >= 128*KTOT) return;
    int o = idx / KTOT, kk = idx % KTOT;
    float v = w[(long)kk*128 + o];
    __half hi = __float2half(v);
    wt[idx] = hi;
    wt[(long)128*KTOT + idx] = __float2half((v - __half2float(hi)) * LO_SCALE);
}

// ---------------------------------------------------------------------------
// HLIF scan, DEPTH-deep software prefetch (per-kernel tuned depth).
// ---------------------------------------------------------------------------
template<int C, int Rp, int PFp, int DEPTH>
__global__ __launch_bounds__(128)
void hlif_kernel(const float* __restrict__ xin, float* __restrict__ spk,
                 __half* __restrict__ spkh,
                 const float* __restrict__ vth_raw,
                 const float* __restrict__ decay_raw,
                 float v_m, float v_s, float d_m, float d_s) {
    int idx = blockIdx.x*128 + threadIdx.x;
    int b = idx / C, c = idx % C;
    float vth = log1pf(expf(vth_raw[c]*v_s + v_m)) + 0.5f;
    float decay = fminf(1.f/(1.f + expf(-(decay_raw[c]*d_s + d_m))), 0.99f);
    long base = (long)b*T_*C + c;
    long bb   = ((long)b*Rp + PFp)*C + c;
    float v = 0.f;
    float xv[DEPTH], xn[DEPTH];
    #pragma unroll
    for (int j = 0; j < DEPTH; j++) xv[j] = xin[base + (long)j*C];
    for (int t = 0; t < T_; t += DEPTH) {
        if (t + DEPTH < T_) {
            #pragma unroll
            for (int j = 0; j < DEPTH; j++) xn[j] = xin[base + (long)(t+DEPTH+j)*C];
        }
        #pragma unroll
        for (int j = 0; j < DEPTH; j++) {
            v = v*decay + xv[j];
            float s = (v - vth) > 0.f ? 1.f : 0.f;
            v -= s*vth;
            spk[base + (long)(t+j)*C] = s;
            spkh[bb + (long)(t+j)*C] = __float2half(s);
        }
        #pragma unroll
        for (int j = 0; j < DEPTH; j++) xv[j] = xn[j];
    }
}

// ---------------------------------------------------------------------------
// ALIF scan, 32-deep software prefetch.
// ---------------------------------------------------------------------------
__global__ __launch_bounds__(128)
void alif_kernel(const float* __restrict__ xin, float* __restrict__ spk) {
    const float d = 0.9f, adp = 0.9f, beta = 1.8f;
    int idx = blockIdx.x*128 + threadIdx.x;
    int b = idx / C3, c = idx % C3;
    long base = (long)b*T_*C3 + c;
    float v = 0.f, th = 0.f, ps = 0.f;
    float xv[32], xn[32];
    #pragma unroll
    for (int j = 0; j < 32; j++) xv[j] = xin[base + (long)j*C3];
    for (int t = 0; t < T_; t += 32) {
        if (t + 32 < T_) {
            #pragma unroll
            for (int j = 0; j < 32; j++) xn[j] = xin[base + (long)(t+32+j)*C3];
        }
        #pragma unroll
        for (int j = 0; j < 32; j++) {
            th = th*adp + ps*beta;
            v  = v*d + xv[j];
            float vt = 0.5f + th;
            float s = (v - vt) > 0.f ? 1.f : 0.f;
            v -= s*vt;
            ps = s;
            spk[base + (long)(t+j)*C3] = s;
        }
        #pragma unroll
        for (int j = 0; j < 32; j++) xv[j] = xn[j];
    }
}

// ---------------------------------------------------------------------------
// HMMA dilated conv + BN (R8/R10 config). CTA 128(t) x 64(cout), 2 CTAs/SM,
// grid (4, 2, B) = 1024 CTAs, 3-stage cp.async, hi/lo fp16 limb accs.
// Stage = A(16KB) + Bhi(8KB) + Blo(8KB) = 32KB; x3 stages = 96KB dynamic.
// ---------------------------------------------------------------------------
#define STAGE_BYTES 32768
#define CSMEM_BYTES (3*STAGE_BYTES)

template<int CIN, int DIL, int PADL, int PF, int Rp, int NITER>
__global__ __launch_bounds__(256, 2)
void conv_mma_kernel(const __half* __restrict__ src, const __half* __restrict__ wt,
                     const float* __restrict__ sc, const float* __restrict__ bi,
                     const float* __restrict__ mn, const float* __restrict__ vr,
                     float* __restrict__ dst) {
    constexpr int KTOT = NITER*64;
    constexpr int CHUNKS = CIN/64;
    extern __shared__ char smem[];
    __shared__ float gsm[64], hbm[64];
    const int tid = threadIdx.x, lane = tid & 31, wid = tid >> 5;
    const int warpM = wid & 3, warpN = wid >> 2;   // 4(M) x 2(N)
    const int mtile = blockIdx.x, oBase = blockIdx.y*64, b = blockIdx.z;

    if (tid < 64) {
        int o = oBase + tid;
        float inv = rsqrtf(vr[o] + 1e-5f);
        float g = sc[o]*inv;
        gsm[tid] = g;
        hbm[tid] = bi[o] - mn[o]*g;
    }

    const uint32_t sbase = smem_to_u32(smem);
    const __half* sb = src + (long)b*Rp*CIN;

    float accH[2][4][4] = {};
    float accL[2][4][4] = {};

    auto issue = [&](int it) {
        const uint32_t stage = sbase + (uint32_t)(it % 3)*(uint32_t)STAGE_BYTES;
        const int k  = it / CHUNKS;
        const int c0 = (it % CHUNKS)*64;
        const long arow0 = (long)(PF + mtile*128 + k*DIL - PADL);
        #pragma unroll
        for (int rep = 0; rep < 4; rep++) {
            int idx = rep*256 + tid;
            int row = idx >> 3, seg = idx & 7;
            const __half* gp = sb + (arow0 + row)*CIN + c0 + seg*8;
            CP_ASYNC16(stage + SWZ(row*128 + seg*16), gp);
        }
        #pragma unroll
        for (int limb = 0; limb < 2; limb++) {
            const __half* wp = wt + (long)limb*128*KTOT + (long)oBase*KTOT + it*64;
            #pragma unroll
            for (int rep = 0; rep < 2; rep++) {
                int idx = rep*256 + tid;
                int row = idx >> 3, seg = idx & 7;
                const __half* gp = wp + (long)row*KTOT + seg*8;
                CP_ASYNC16(stage + 16384u + (uint32_t)limb*8192u + SWZ(row*128 + seg*16), gp);
            }
        }
        CP_COMMIT();
    };

    issue(0);
    issue(1);
    __syncthreads();

    for (int it = 0; it < NITER; it++) {
        if (it + 2 < NITER) CP_WAIT1(); else CP_WAIT0();
        __syncthreads();
        if (it + 2 < NITER) issue(it + 2);

        const uint32_t stage = sbase + (uint32_t)(it % 3)*(uint32_t)STAGE_BYTES;

        #pragma unroll
        for (int ks = 0; ks < 4; ks++) {
            uint32_t a[2][4];
            #pragma unroll
            for (int mf = 0; mf < 2; mf++) {
                int row = warpM*32 + mf*16 + (lane & 15);
                LDSM_X4(a[mf], stage + SWZ(row*128 + ks*32 + (lane >> 4)*16));
            }
            #pragma unroll
            for (int limb = 0; limb < 2; limb++) {
                const uint32_t bbp = stage + 16384u + (uint32_t)limb*8192u;
                #pragma unroll
                for (int np = 0; np < 2; np++) {
                    int row = warpN*32 + np*16 + ((lane >> 4) << 3) + (lane & 7);
                    uint32_t q[4];
                    LDSM_X4(q, bbp + SWZ(row*128 + ks*32 + ((lane >> 3) & 1)*16));
                    if (limb == 0) {
                        #pragma unroll
                        for (int mf = 0; mf < 2; mf++) {
                            MMA16816(accH[mf][np*2],     a[mf], q[0], q[1]);
                            MMA16816(accH[mf][np*2 + 1], a[mf], q[2], q[3]);
                        }
                    } else {
                        #pragma unroll
                        for (int mf = 0; mf < 2; mf++) {
                            MMA16816(accL[mf][np*2],     a[mf], q[0], q[1]);
                            MMA16816(accL[mf][np*2 + 1], a[mf], q[2], q[3]);
                        }
                    }
                }
            }
        }
    }

    #pragma unroll
    for (int mf = 0; mf < 2; mf++) {
        #pragma unroll
        for (int h = 0; h < 2; h++) {
            int t = mtile*128 + warpM*32 + mf*16 + (lane >> 2) + h*8;
            if (t < T_) {
                long dr = ((long)b*T_ + t)*128 + oBase;
                #pragma unroll
                for (int ng = 0; ng < 4; ng++) {
                    int lc = warpN*32 + ng*8 + (lane & 3)*2;
                    float v0 = fmaf(accL[mf][ng][h*2],     LO_INV, accH[mf][ng][h*2]);
                    float v1 = fmaf(accL[mf][ng][h*2 + 1], LO_INV, accH[mf][ng][h*2 + 1]);
                    float2 o;
                    o.x = fmaf(v0, gsm[lc],   hbm[lc]);
                    o.y = fmaf(v1, gsm[lc+1], hbm[lc+1]);
                    *(float2*)&dst[dr + lc] = o;
                }
            }
        }
    }
}

// ---------------------------------------------------------------------------
// Readout: dense -> LI scan -> window diff -> attention -> logits
// ---------------------------------------------------------------------------
__global__ __launch_bounds__(256)
void readout_kernel(const float* __restrict__ spk3,
                    const float* __restrict__ dw, const float* __restrict__ db,
                    const float* __restrict__ a1w, const float* __restrict__ a1b,
                    const float* __restrict__ a2w, const float* __restrict__ a2b,
                    float* __restrict__ logits) {
    __shared__ float vseq[T_*4];
    __shared__ float dp[20*4];
    __shared__ float hsm[20*8];
    __shared__ float score[20];
    __shared__ float wsm[128*4];
    int b = blockIdx.x, tid = threadIdx.x;
    for (int e = tid; e < 512; e += 256) wsm[e] = dw[e];
    __syncthreads();
    const float* sp = spk3 + (long)b*T_*C3;
    for (int e = tid; e < T_*4; e += 256) {
        int t = e >> 2, j = e & 3;
        float accv = db[j];
        const float* row = sp + (long)t*C3;
        #pragma unroll 8
        for (int c = 0; c < 128; c++) accv = fmaf(row[c], wsm[c*4 + j], accv);
        vseq[e] = accv;
    }
    __syncthreads();
    if (tid < 4) {
        float v = 0.f;
        const float dec = 0.9f, odec = 0.1f;
        for (int t = 0; t < T_; t++) {
            v = fmaf(v, dec, vseq[t*4 + tid]*odec);
            vseq[t*4 + tid] = v;
        }
    }
    __syncthreads();
    if (tid < 80) {
        int g = tid >> 2, j = tid & 3;
        float s1 = 0.f, s2 = 0.f;
        #pragma unroll
        for (int u = 0; u < 12; u++) {
            s1 += vseq[(g*24 + u)*4 + j];
            s2 += vseq[(g*24 + 12 + u)*4 + j];
        }
        dp[g*4 + j] = (s2 - s1)*(1.f/12.f);
    }
    __syncthreads();
    if (tid < 160) {
        int g = tid >> 3, u = tid & 7;
        float a = a1b[u];
        #pragma unroll
        for (int j = 0; j < 4; j++) a = fmaf(dp[g*4 + j], a1w[j*8 + u], a);
        hsm[g*8 + u] = fmaxf(a, 0.f);
    }
    __syncthreads();
    if (tid < 20) {
        float a = a2b[0];
        #pragma unroll
        for (int u = 0; u < 8; u++) a = fmaf(hsm[tid*8 + u], a2w[u], a);
        score[tid] = a;
    }
    __syncthreads();
    if (tid < 4) {
        float m = -1e30f;
        #pragma unroll
        for (int g = 0; g < 20; g++) m = fmaxf(m, score[g]);
        float den = 0.f, accv = 0.f;
        #pragma unroll
        for (int g = 0; g < 20; g++) {
            float e = expf(score[g] - m);
            den += e;
            accv = fmaf(dp[g*4 + tid], e, accv);
        }
        logits[b*4 + tid] = accv/den;
    }
}

// ---------------------------------------------------------------------------
extern "C" void kernel_launch(void* const* d_in, const int* in_sizes, int n_in,
                              void* d_out, int out_size) {
    const float* x    = (const float*)d_in[0];
    const float* w1   = (const float*)d_in[1];
    const float* bn1s = (const float*)d_in[2];
    const float* bn1b = (const float*)d_in[3];
    const float* bn1m = (const float*)d_in[4];
    const float* bn1v = (const float*)d_in[5];
    const float* vth1 = (const float*)d_in[6];
    const float* dec1 = (const float*)d_in[7];
    const float* w2   = (const float*)d_in[8];
    const float* bn2s = (const float*)d_in[9];
    const float* bn2b = (const float*)d_in[10];
    const float* bn2m = (const float*)d_in[11];
    const float* bn2v = (const float*)d_in[12];
    const float* vth2 = (const float*)d_in[13];
    const float* dec2 = (const float*)d_in[14];
    const float* w3   = (const float*)d_in[15];
    const float* bn3s = (const float*)d_in[16];
    const float* bn3b = (const float*)d_in[17];
    const float* bn3m = (const float*)d_in[18];
    const float* bn3v = (const float*)d_in[19];
    const float* dw   = (const float*)d_in[20];
    const float* db   = (const float*)d_in[21];
    const float* a1w  = (const float*)d_in[22];
    const float* a1b  = (const float*)d_in[23];
    const float* a2w  = (const float*)d_in[24];
    const float* a2b  = (const float*)d_in[25];

    float* out  = (float*)d_out;
    float* spk1 = out + 512;
    float* spk2 = spk1 + S1_;
    float* spk3 = spk2 + S2_;

    void *px1, *px2, *px3, *psp, *pw2, *pw3;
    cudaGetSymbolAddress(&px1, g_x1);
    cudaGetSymbolAddress(&px2, g_x2);
    cudaGetSymbolAddress(&px3, g_x3);
    cudaGetSymbolAddress(&psp, g_spkh);
    cudaGetSymbolAddress(&pw2, g_wt2);
    cudaGetSymbolAddress(&pw3, g_wt3);
    float* x1p = (float*)px1;
    float* x2p = (float*)px2;
    float* x3p = (float*)px3;
    __half* s1h = (__half*)psp;
    __half* s2h = s1h + SPK1_ELEMS;
    __half* wt2 = (__half*)pw2;
    __half* wt3 = (__half*)pw3;

    cudaFuncSetAttribute(conv_mma_kernel<C1, 4, 62, P1F, R1_, 32>,
                         cudaFuncAttributeMaxDynamicSharedMemorySize, CSMEM_BYTES);
    cudaFuncSetAttribute(conv_mma_kernel<C2, 12, 186, P2F, R2_, 64>,
                         cudaFuncAttributeMaxDynamicSharedMemorySize, CSMEM_BYTES);

    // Launch order (ncu -s 5 -c 1 => index 5 = conv2):
    // 0: wprep2 hi, 1: wprep2 lo, 2: wprep3, 3: conv1, 4: hlif1, 5: conv2
    wprep_kernel<0><<<(128*2048 + 255)/256, 256>>>(w2, wt2, 2048);
    wprep_kernel<1><<<(128*2048 + 255)/256, 256>>>(w2, wt2, 2048);
    wprep_both_kernel<<<(128*4096 + 255)/256, 256>>>(w3, wt3, 4096);

    conv1_bn_kernel<<<B_*T_/64, 256>>>(x, w1, bn1s, bn1b, bn1m, bn1v, x1p);
    hlif_kernel<C1, R1_, P1F, 16><<<B_*C1/128, 128>>>(x1p, spk1, s1h, vth1, dec1,
                                                      0.f, 1.f, 2.f, 1.f);
    conv_mma_kernel<C1, 4, 62, P1F, R1_, 32><<<dim3(4, 2, B_), 256, CSMEM_BYTES>>>(
        s1h, wt2, bn2s, bn2b, bn2m, bn2v, x2p);
    hlif_kernel<C2, R2_, P2F, 32><<<B_*C2/128, 128>>>(x2p, spk2, s2h, vth2, dec2,
                                                      0.f, 1.f, 2.f, 1.f);
    conv_mma_kernel<C2, 12, 186, P2F, R2_, 64><<<dim3(4, 2, B_), 256, CSMEM_BYTES>>>(
        s2h, wt3, bn3s, bn3b, bn3m, bn3v, x3p);
    alif_kernel<<<B_*C3/128, 128>>>(x3p, spk3);
    readout_kernel<<<B_, 256>>>(spk3, dw, db, a1w, a1b, a2w, a2b, out);
}